// round 2
// baseline (speedup 1.0000x reference)
#include <cuda_runtime.h>
#include <cstdint>
#include <math.h>

#define NN 50000
#define DD 256
#define GG 64

// ---------------- static device scratch (no allocations allowed) ----------------
__device__ float4 g_hs4[NN * DD / 4];   // hs = dis * (X @ W)
__device__ float4 g_t4[NN * DD / 4];    // scatter accumulator
__device__ float4 g_act4[NN * DD / 4];  // layer activation (tanh output)
__device__ float  g_deg[NN];
__device__ float  g_dis[NN];
__device__ int    g_cnt[GG];
__device__ int    g_start[GG];
__device__ float  g_pool[GG * 2 * DD];
__device__ float  g_m1[GG * 512];
__device__ float  g_m2[GG * 256];

// ---------------- degree / norm ----------------
__global__ void deg_kernel(const int* __restrict__ ei, int E) {
    int e = blockIdx.x * blockDim.x + threadIdx.x;
    if (e < E) {
        int dst = ei[E + e];
        atomicAdd(&g_deg[dst], 1.0f);
    }
}

__global__ void dis_kernel(int n) {
    int i = blockIdx.x * blockDim.x + threadIdx.x;
    if (i < n) g_dis[i] = rsqrtf(1.0f + g_deg[i]);
}

// ---------------- batch group bookkeeping ----------------
__global__ void count_kernel(const int* __restrict__ bi, int n) {
    int i = blockIdx.x * blockDim.x + threadIdx.x;
    if (i < n) atomicAdd(&g_cnt[bi[i]], 1);
}

__global__ void scan_kernel() {
    if (threadIdx.x == 0 && blockIdx.x == 0) {
        int s = 0;
        for (int g = 0; g < GG; g++) { g_start[g] = s; s += g_cnt[g]; }
    }
}

// ---------------- SGEMM: g_hs = dis[row] * (A[M,KD] @ W[KD,256]) ----------------
// 128x128 block tile, 8x8 per thread, BK=8, 256 threads.
template<int KD>
__global__ __launch_bounds__(256, 1) void gemm_hs(const float* __restrict__ A,
                                                  const float* __restrict__ W,
                                                  int M) {
    __shared__ float As[8][128];
    __shared__ float Bs[8][132];  // pad keeps 16B alignment (132 % 4 == 0)

    const int t  = threadIdx.x;
    const int m0 = blockIdx.y * 128;
    const int n0 = blockIdx.x * 128;
    const int tx = t & 15;
    const int ty = t >> 4;

    float acc[8][8];
#pragma unroll
    for (int i = 0; i < 8; i++)
#pragma unroll
        for (int j = 0; j < 8; j++) acc[i][j] = 0.0f;

    const int arow = t >> 1;          // 0..127
    const int akp  = (t & 1) * 4;     // 0 or 4
    const int brow = t >> 5;          // 0..7
    const int bnp  = (t & 31) * 4;    // 0..124
    const int gr   = m0 + arow;

    for (int k0 = 0; k0 < KD; k0 += 8) {
        float4 av = make_float4(0.f, 0.f, 0.f, 0.f);
        if (gr < M)
            av = *reinterpret_cast<const float4*>(&A[(size_t)gr * KD + k0 + akp]);
        As[akp + 0][arow] = av.x;
        As[akp + 1][arow] = av.y;
        As[akp + 2][arow] = av.z;
        As[akp + 3][arow] = av.w;

        *reinterpret_cast<float4*>(&Bs[brow][bnp]) =
            *reinterpret_cast<const float4*>(&W[(size_t)(k0 + brow) * DD + n0 + bnp]);
        __syncthreads();

#pragma unroll
        for (int k = 0; k < 8; k++) {
            float a[8], b[8];
            *(float4*)&a[0] = *(const float4*)&As[k][ty * 8];
            *(float4*)&a[4] = *(const float4*)&As[k][ty * 8 + 4];
            *(float4*)&b[0] = *(const float4*)&Bs[k][tx * 8];
            *(float4*)&b[4] = *(const float4*)&Bs[k][tx * 8 + 4];
#pragma unroll
            for (int i = 0; i < 8; i++)
#pragma unroll
                for (int j = 0; j < 8; j++)
                    acc[i][j] = fmaf(a[i], b[j], acc[i][j]);
        }
        __syncthreads();
    }

    float* C = (float*)g_hs4;
#pragma unroll
    for (int i = 0; i < 8; i++) {
        int r = m0 + ty * 8 + i;
        if (r < M) {
            float dv = g_dis[r];
            float4 o0 = make_float4(dv * acc[i][0], dv * acc[i][1],
                                    dv * acc[i][2], dv * acc[i][3]);
            float4 o1 = make_float4(dv * acc[i][4], dv * acc[i][5],
                                    dv * acc[i][6], dv * acc[i][7]);
            *(float4*)&C[(size_t)r * DD + n0 + tx * 8]     = o0;
            *(float4*)&C[(size_t)r * DD + n0 + tx * 8 + 4] = o1;
        }
    }
}

// ---------------- edge scatter: t[dst] += hs[src], one warp per edge ----------------
__global__ void scatter_kernel(const int* __restrict__ ei, int E) {
    int w    = (int)(((unsigned)blockIdx.x * blockDim.x + threadIdx.x) >> 5);
    int lane = threadIdx.x & 31;
    if (w >= E) return;
    int src = ei[w];
    int dst = ei[E + w];
    const float4* hsr = g_hs4 + (size_t)src * (DD / 4);
    float4*       tr  = g_t4  + (size_t)dst * (DD / 4);
#pragma unroll
    for (int c = lane; c < DD / 4; c += 32) {
        float4 v = __ldg(&hsr[c]);
        asm volatile("red.global.add.v4.f32 [%0], {%1,%2,%3,%4};"
                     :: "l"(tr + c), "f"(v.x), "f"(v.y), "f"(v.z), "f"(v.w)
                     : "memory");
    }
}

// ---------------- combine + tanh: act = tanh(dis*(t + hs) + b) ----------------
__global__ void combine_kernel(const float* __restrict__ bias, int n4) {
    int i = blockIdx.x * blockDim.x + threadIdx.x;
    if (i >= n4) return;
    int node = i >> 6;
    int fb   = i & 63;
    float d  = g_dis[node];
    float4 tv = g_t4[i];
    float4 hv = g_hs4[i];
    float4 bv = reinterpret_cast<const float4*>(bias)[fb];
    float4 o;
    o.x = tanhf(fmaf(d, tv.x + hv.x, bv.x));
    o.y = tanhf(fmaf(d, tv.y + hv.y, bv.y));
    o.z = tanhf(fmaf(d, tv.z + hv.z, bv.z));
    o.w = tanhf(fmaf(d, tv.w + hv.w, bv.w));
    g_act4[i] = o;
}

// ---------------- per-graph max + mean pooling (batch_index is sorted) ----------------
__global__ void pool_kernel() {
    int g = blockIdx.x;
    int f = threadIdx.x;  // 256 threads = one feature each
    int s = g_start[g];
    int c = g_cnt[g];
    const float* act = (const float*)g_act4;
    float mx = -INFINITY, sm = 0.f;
    for (int r = 0; r < c; r++) {
        float v = act[(size_t)(s + r) * DD + f];
        mx = fmaxf(mx, v);
        sm += v;
    }
    g_pool[g * (2 * DD) + f]      = mx;
    g_pool[g * (2 * DD) + DD + f] = sm / fmaxf((float)c, 1.0f);
}

// ---------------- tiny MLP: C[row] = act(A[row] @ W + b) ----------------
template<bool RELU>
__global__ void mlp_kernel(const float* __restrict__ A, const float* __restrict__ W,
                           const float* __restrict__ bias, float* __restrict__ C,
                           int K, int Nc) {
    __shared__ float sA[512];
    int row = blockIdx.x;
    for (int k = threadIdx.x; k < K; k += blockDim.x) sA[k] = A[(size_t)row * K + k];
    __syncthreads();
    for (int n = threadIdx.x; n < Nc; n += blockDim.x) {
        float acc = bias[n];
        for (int k = 0; k < K; k++) acc = fmaf(sA[k], W[(size_t)k * Nc + n], acc);
        C[(size_t)row * Nc + n] = RELU ? fmaxf(acc, 0.f) : acc;
    }
}

// ---------------- launch ----------------
extern "C" void kernel_launch(void* const* d_in, const int* in_sizes, int n_in,
                              void* d_out, int out_size) {
    const float* x   = (const float*)d_in[0];
    const int*   ei  = (const int*)d_in[1];   // int32! (JAX x64 disabled)
    const int*   bi  = (const int*)d_in[2];   // int32!
    const float* W0 = (const float*)d_in[3];  const float* b0 = (const float*)d_in[4];
    const float* W1 = (const float*)d_in[5];  const float* b1 = (const float*)d_in[6];
    const float* W2 = (const float*)d_in[7];  const float* b2 = (const float*)d_in[8];
    const float* W3 = (const float*)d_in[9];  const float* b3 = (const float*)d_in[10];
    const float* fc1w = (const float*)d_in[11]; const float* fc1b = (const float*)d_in[12];
    const float* fc2w = (const float*)d_in[13]; const float* fc2b = (const float*)d_in[14];
    const float* ow   = (const float*)d_in[15]; const float* ob   = (const float*)d_in[16];

    const int F = 128;
    int N = in_sizes[0] / F;
    int E = in_sizes[1] / 2;

    void *p_deg, *p_t, *p_cnt, *p_act, *p_pool, *p_m1, *p_m2;
    cudaGetSymbolAddress(&p_deg,  g_deg);
    cudaGetSymbolAddress(&p_t,    g_t4);
    cudaGetSymbolAddress(&p_cnt,  g_cnt);
    cudaGetSymbolAddress(&p_act,  g_act4);
    cudaGetSymbolAddress(&p_pool, g_pool);
    cudaGetSymbolAddress(&p_m1,   g_m1);
    cudaGetSymbolAddress(&p_m2,   g_m2);

    cudaMemsetAsync(p_deg, 0, (size_t)N * sizeof(float), 0);
    cudaMemsetAsync(p_cnt, 0, GG * sizeof(int), 0);

    deg_kernel<<<(E + 255) / 256, 256>>>(ei, E);
    dis_kernel<<<(N + 255) / 256, 256>>>(N);
    count_kernel<<<(N + 255) / 256, 256>>>(bi, N);
    scan_kernel<<<1, 32>>>();

    dim3 ggrid(2, (N + 127) / 128);
    int n4 = N * (DD / 4);
    size_t tbytes = (size_t)N * DD * sizeof(float);
    long long warpthreads = (long long)E * 32;
    int sblocks = (int)((warpthreads + 255) / 256);

    const float* Ws[4] = {W0, W1, W2, W3};
    const float* bs[4] = {b0, b1, b2, b3};
    for (int layer = 0; layer < 4; layer++) {
        if (layer == 0) gemm_hs<128><<<ggrid, 256>>>(x, Ws[0], N);
        else            gemm_hs<256><<<ggrid, 256>>>((const float*)p_act, Ws[layer], N);
        cudaMemsetAsync(p_t, 0, tbytes, 0);
        scatter_kernel<<<sblocks, 256>>>(ei, E);
        combine_kernel<<<(n4 + 255) / 256, 256>>>(bs[layer], n4);
    }

    pool_kernel<<<GG, DD>>>();
    mlp_kernel<true ><<<GG, 256>>>((const float*)p_pool, fc1w, fc1b, (float*)p_m1, 2 * DD, 512);
    mlp_kernel<true ><<<GG, 256>>>((const float*)p_m1,   fc2w, fc2b, (float*)p_m2, 512, 256);
    mlp_kernel<false><<<GG, 32 >>>((const float*)p_m2,   ow,   ob,   (float*)d_out, 256, 10);
}

// round 3
// speedup vs baseline: 1.4365x; 1.4365x over previous
#include <cuda_runtime.h>
#include <cstdint>
#include <math.h>

#define NN 50000
#define EE 1600000
#define DD 256
#define GG 64

// ---------------- static device scratch (no allocations allowed) ----------------
__device__ float4 g_hs4[NN * DD / 4];   // hs = dis * (A @ W)
__device__ float4 g_act4[NN * DD / 4];  // layer activation (tanh output)
__device__ float  g_dis[NN];
__device__ int    g_degi[NN];
__device__ int    g_rowstart[NN + 1];
__device__ int    g_cursor[NN];
__device__ int    g_bsum[256];
__device__ int    g_boff[256];
__device__ int    g_csr[EE];
__device__ int    g_cnt[GG];
__device__ int    g_start[GG];
__device__ float  g_pool[GG * 2 * DD];
__device__ float  g_m1[GG * 512];
__device__ float  g_m2[GG * 256];

// ---------------- degree histogram / norm ----------------
__global__ void deg_kernel(const int* __restrict__ ei, int E) {
    int e = blockIdx.x * blockDim.x + threadIdx.x;
    if (e < E) atomicAdd(&g_degi[ei[E + e]], 1);
}

__global__ void dis_kernel(int n) {
    int i = blockIdx.x * blockDim.x + threadIdx.x;
    if (i < n) g_dis[i] = rsqrtf(1.0f + (float)g_degi[i]);
}

// ---------------- CSR build: 2-level exclusive scan over degrees ----------------
__global__ void scan1_kernel(int n) {
    __shared__ int sh[256];
    int t = threadIdx.x;
    int i = blockIdx.x * 256 + t;
    int v = (i < n) ? g_degi[i] : 0;
    sh[t] = v;
    __syncthreads();
#pragma unroll
    for (int off = 1; off < 256; off <<= 1) {
        int x = (t >= off) ? sh[t - off] : 0;
        __syncthreads();
        sh[t] += x;
        __syncthreads();
    }
    if (i < n) g_rowstart[i] = sh[t] - v;   // block-local exclusive
    if (t == 255) g_bsum[blockIdx.x] = sh[255];
}

__global__ void scan2_kernel(int nb, int n) {
    __shared__ int sh[256];
    int t = threadIdx.x;
    int v = (t < nb) ? g_bsum[t] : 0;
    sh[t] = v;
    __syncthreads();
#pragma unroll
    for (int off = 1; off < 256; off <<= 1) {
        int x = (t >= off) ? sh[t - off] : 0;
        __syncthreads();
        sh[t] += x;
        __syncthreads();
    }
    if (t < nb) g_boff[t] = sh[t] - v;      // exclusive block offsets
    if (t == 255) g_rowstart[n] = sh[255];  // total = E
}

__global__ void scan3_kernel(int n) {
    int i = blockIdx.x * 256 + threadIdx.x;
    if (i < n) {
        int r = g_rowstart[i] + g_boff[blockIdx.x];
        g_rowstart[i] = r;
        g_cursor[i] = r;
    }
}

__global__ void fill_kernel(const int* __restrict__ ei, int E) {
    int e = blockIdx.x * blockDim.x + threadIdx.x;
    if (e < E) {
        int dst = ei[E + e];
        int p = atomicAdd(&g_cursor[dst], 1);
        g_csr[p] = ei[e];
    }
}

// ---------------- batch group bookkeeping ----------------
__global__ void count_kernel(const int* __restrict__ bi, int n) {
    int i = blockIdx.x * blockDim.x + threadIdx.x;
    if (i < n) atomicAdd(&g_cnt[bi[i]], 1);
}

__global__ void gscan_kernel() {
    if (threadIdx.x == 0) {
        int s = 0;
        for (int g = 0; g < GG; g++) { g_start[g] = s; s += g_cnt[g]; }
    }
}

// ---------------- SGEMM (double-buffered): g_hs = dis[row]*(A[M,KD] @ W[KD,256]) --
template<int KD>
__global__ __launch_bounds__(256, 1) void gemm_hs(const float* __restrict__ A,
                                                  const float* __restrict__ W,
                                                  int M) {
    __shared__ float As[2][8][128];
    __shared__ float Bs[2][8][132];

    const int t  = threadIdx.x;
    const int m0 = blockIdx.y * 128;
    const int n0 = blockIdx.x * 128;
    const int tx = t & 15;
    const int ty = t >> 4;

    float acc[8][8];
#pragma unroll
    for (int i = 0; i < 8; i++)
#pragma unroll
        for (int j = 0; j < 8; j++) acc[i][j] = 0.0f;

    const int arow = t >> 1;          // 0..127
    const int akp  = (t & 1) * 4;     // 0 or 4
    const int brow = t >> 5;          // 0..7
    const int bnp  = (t & 31) * 4;    // 0..124
    const int gr   = m0 + arow;

    // prefetch tile 0 into buffer 0
    {
        float4 av = make_float4(0.f, 0.f, 0.f, 0.f);
        if (gr < M) av = *reinterpret_cast<const float4*>(&A[(size_t)gr * KD + akp]);
        As[0][akp + 0][arow] = av.x;
        As[0][akp + 1][arow] = av.y;
        As[0][akp + 2][arow] = av.z;
        As[0][akp + 3][arow] = av.w;
        *reinterpret_cast<float4*>(&Bs[0][brow][bnp]) =
            *reinterpret_cast<const float4*>(&W[(size_t)brow * DD + n0 + bnp]);
    }
    __syncthreads();

    int buf = 0;
    for (int k0 = 0; k0 < KD; k0 += 8) {
        float4 pav = make_float4(0.f, 0.f, 0.f, 0.f), pbv;
        const bool has = (k0 + 8 < KD);
        if (has) {
            if (gr < M)
                pav = *reinterpret_cast<const float4*>(&A[(size_t)gr * KD + k0 + 8 + akp]);
            pbv = *reinterpret_cast<const float4*>(&W[(size_t)(k0 + 8 + brow) * DD + n0 + bnp]);
        }

#pragma unroll
        for (int k = 0; k < 8; k++) {
            float a[8], b[8];
            *(float4*)&a[0] = *(const float4*)&As[buf][k][ty * 8];
            *(float4*)&a[4] = *(const float4*)&As[buf][k][ty * 8 + 4];
            *(float4*)&b[0] = *(const float4*)&Bs[buf][k][tx * 8];
            *(float4*)&b[4] = *(const float4*)&Bs[buf][k][tx * 8 + 4];
#pragma unroll
            for (int i = 0; i < 8; i++)
#pragma unroll
                for (int j = 0; j < 8; j++)
                    acc[i][j] = fmaf(a[i], b[j], acc[i][j]);
        }

        if (has) {
            As[buf ^ 1][akp + 0][arow] = pav.x;
            As[buf ^ 1][akp + 1][arow] = pav.y;
            As[buf ^ 1][akp + 2][arow] = pav.z;
            As[buf ^ 1][akp + 3][arow] = pav.w;
            *reinterpret_cast<float4*>(&Bs[buf ^ 1][brow][bnp]) = pbv;
        }
        __syncthreads();
        buf ^= 1;
    }

    float* C = (float*)g_hs4;
#pragma unroll
    for (int i = 0; i < 8; i++) {
        int r = m0 + ty * 8 + i;
        if (r < M) {
            float dv = g_dis[r];
            float4 o0 = make_float4(dv * acc[i][0], dv * acc[i][1],
                                    dv * acc[i][2], dv * acc[i][3]);
            float4 o1 = make_float4(dv * acc[i][4], dv * acc[i][5],
                                    dv * acc[i][6], dv * acc[i][7]);
            *(float4*)&C[(size_t)r * DD + n0 + tx * 8]     = o0;
            *(float4*)&C[(size_t)r * DD + n0 + tx * 8 + 4] = o1;
        }
    }
}

// ---------------- fused CSR aggregate + tanh ----------------
// act[dst] = tanh(dis[dst] * (hs[dst] + sum_{e in row(dst)} hs[src_e]) + b)
// 64 threads (float4 each) per node, 4 nodes per 256-thread block.
__global__ __launch_bounds__(256) void aggregate_kernel(const float* __restrict__ bias,
                                                        int n) {
    int node = blockIdx.x * 4 + (threadIdx.x >> 6);
    int f4   = threadIdx.x & 63;
    if (node >= n) return;

    int s = g_rowstart[node];
    int e = g_rowstart[node + 1];

    float4 acc = g_hs4[(size_t)node * 64 + f4];  // self contribution

    int i = s;
    for (; i + 4 <= e; i += 4) {
        int s0 = __ldg(&g_csr[i]);
        int s1 = __ldg(&g_csr[i + 1]);
        int s2 = __ldg(&g_csr[i + 2]);
        int s3 = __ldg(&g_csr[i + 3]);
        float4 v0 = __ldg(&g_hs4[(size_t)s0 * 64 + f4]);
        float4 v1 = __ldg(&g_hs4[(size_t)s1 * 64 + f4]);
        float4 v2 = __ldg(&g_hs4[(size_t)s2 * 64 + f4]);
        float4 v3 = __ldg(&g_hs4[(size_t)s3 * 64 + f4]);
        acc.x += (v0.x + v1.x) + (v2.x + v3.x);
        acc.y += (v0.y + v1.y) + (v2.y + v3.y);
        acc.z += (v0.z + v1.z) + (v2.z + v3.z);
        acc.w += (v0.w + v1.w) + (v2.w + v3.w);
    }
    for (; i < e; i++) {
        int s0 = __ldg(&g_csr[i]);
        float4 v = __ldg(&g_hs4[(size_t)s0 * 64 + f4]);
        acc.x += v.x; acc.y += v.y; acc.z += v.z; acc.w += v.w;
    }

    float d = g_dis[node];
    float4 bv = reinterpret_cast<const float4*>(bias)[f4];
    float4 o;
    o.x = tanhf(fmaf(d, acc.x, bv.x));
    o.y = tanhf(fmaf(d, acc.y, bv.y));
    o.z = tanhf(fmaf(d, acc.z, bv.z));
    o.w = tanhf(fmaf(d, acc.w, bv.w));
    g_act4[(size_t)node * 64 + f4] = o;
}

// ---------------- per-graph max + mean pooling (batch_index is sorted) ----------------
__global__ void pool_kernel() {
    int g = blockIdx.x;
    int f = threadIdx.x;  // 256 threads = one feature each
    int s = g_start[g];
    int c = g_cnt[g];
    const float* act = (const float*)g_act4;
    float mx = -INFINITY, sm = 0.f;
    for (int r = 0; r < c; r++) {
        float v = act[(size_t)(s + r) * DD + f];
        mx = fmaxf(mx, v);
        sm += v;
    }
    g_pool[g * (2 * DD) + f]      = mx;
    g_pool[g * (2 * DD) + DD + f] = sm / fmaxf((float)c, 1.0f);
}

// ---------------- tiny MLP: C[row] = act(A[row] @ W + b) ----------------
template<bool RELU>
__global__ void mlp_kernel(const float* __restrict__ A, const float* __restrict__ W,
                           const float* __restrict__ bias, float* __restrict__ C,
                           int K, int Nc) {
    __shared__ float sA[512];
    int row = blockIdx.x;
    for (int k = threadIdx.x; k < K; k += blockDim.x) sA[k] = A[(size_t)row * K + k];
    __syncthreads();
    for (int n = threadIdx.x; n < Nc; n += blockDim.x) {
        float acc = bias[n];
        for (int k = 0; k < K; k++) acc = fmaf(sA[k], W[(size_t)k * Nc + n], acc);
        C[(size_t)row * Nc + n] = RELU ? fmaxf(acc, 0.f) : acc;
    }
}

// ---------------- launch ----------------
extern "C" void kernel_launch(void* const* d_in, const int* in_sizes, int n_in,
                              void* d_out, int out_size) {
    const float* x   = (const float*)d_in[0];
    const int*   ei  = (const int*)d_in[1];   // int32 (JAX x64 disabled)
    const int*   bi  = (const int*)d_in[2];   // int32
    const float* W0 = (const float*)d_in[3];  const float* b0 = (const float*)d_in[4];
    const float* W1 = (const float*)d_in[5];  const float* b1 = (const float*)d_in[6];
    const float* W2 = (const float*)d_in[7];  const float* b2 = (const float*)d_in[8];
    const float* W3 = (const float*)d_in[9];  const float* b3 = (const float*)d_in[10];
    const float* fc1w = (const float*)d_in[11]; const float* fc1b = (const float*)d_in[12];
    const float* fc2w = (const float*)d_in[13]; const float* fc2b = (const float*)d_in[14];
    const float* ow   = (const float*)d_in[15]; const float* ob   = (const float*)d_in[16];

    const int F = 128;
    int N = in_sizes[0] / F;
    int E = in_sizes[1] / 2;
    int NB = (N + 255) / 256;

    void *p_degi, *p_cnt, *p_act, *p_pool, *p_m1, *p_m2;
    cudaGetSymbolAddress(&p_degi, g_degi);
    cudaGetSymbolAddress(&p_cnt,  g_cnt);
    cudaGetSymbolAddress(&p_act,  g_act4);
    cudaGetSymbolAddress(&p_pool, g_pool);
    cudaGetSymbolAddress(&p_m1,   g_m1);
    cudaGetSymbolAddress(&p_m2,   g_m2);

    cudaMemsetAsync(p_degi, 0, (size_t)N * sizeof(int), 0);
    cudaMemsetAsync(p_cnt, 0, GG * sizeof(int), 0);

    // degree + norm + CSR build (once per launch, reused by all 4 layers)
    deg_kernel<<<(E + 255) / 256, 256>>>(ei, E);
    dis_kernel<<<NB, 256>>>(N);
    scan1_kernel<<<NB, 256>>>(N);
    scan2_kernel<<<1, 256>>>(NB, N);
    scan3_kernel<<<NB, 256>>>(N);
    fill_kernel<<<(E + 255) / 256, 256>>>(ei, E);

    // batch bookkeeping
    count_kernel<<<NB, 256>>>(bi, N);
    gscan_kernel<<<1, 32>>>();

    dim3 ggrid(2, (N + 127) / 128);
    int ablocks = (N + 3) / 4;

    const float* Ws[4] = {W0, W1, W2, W3};
    const float* bs[4] = {b0, b1, b2, b3};
    for (int layer = 0; layer < 4; layer++) {
        if (layer == 0) gemm_hs<128><<<ggrid, 256>>>(x, Ws[0], N);
        else            gemm_hs<256><<<ggrid, 256>>>((const float*)p_act, Ws[layer], N);
        aggregate_kernel<<<ablocks, 256>>>(bs[layer], N);
    }

    pool_kernel<<<GG, DD>>>();
    mlp_kernel<true ><<<GG, 256>>>((const float*)p_pool, fc1w, fc1b, (float*)p_m1, 2 * DD, 512);
    mlp_kernel<true ><<<GG, 256>>>((const float*)p_m1,   fc2w, fc2b, (float*)p_m2, 512, 256);
    mlp_kernel<false><<<GG, 32 >>>((const float*)p_m2,   ow,   ob,   (float*)d_out, 256, 10);
}

// round 5
// speedup vs baseline: 1.9756x; 1.3753x over previous
#include <cuda_runtime.h>
#include <cuda_bf16.h>
#include <cstdint>
#include <math.h>

#define NN 50000
#define EE 1600000
#define DD 256
#define GG 64

// ---------------- static device scratch ----------------
__device__ float4 g_hs4[NN * DD / 4];   // hs = dis * (A @ W)  (fp32)
__device__ float4 g_act4[NN * DD / 4];  // layer activation (tanh output, fp32)
__device__ __nv_bfloat16 g_Ahi[(NN + 128) * DD];  // bf16 hi split of GEMM input A (padded rows)
__device__ __nv_bfloat16 g_Alo[(NN + 128) * DD];  // bf16 lo residual
__device__ __nv_bfloat16 g_Wthi[DD * DD];         // W^T hi  [n][k]
__device__ __nv_bfloat16 g_Wtlo[DD * DD];         // W^T lo  [n][k]
__device__ float  g_dis[NN];
__device__ int    g_degi[NN];
__device__ int    g_rowstart[NN + 1];
__device__ int    g_cursor[NN];
__device__ int    g_bsum[256];
__device__ int    g_boff[256];
__device__ int    g_csr[EE];
__device__ int    g_cnt[GG];
__device__ int    g_start[GG];
__device__ float  g_pool[GG * 2 * DD];
__device__ float  g_m1[GG * 512];
__device__ float  g_m2[GG * 256];

// ---------------- small helpers ----------------
__device__ __forceinline__ uint32_t smem_u32(const void* p) {
    uint32_t a;
    asm("{ .reg .u64 t; cvta.to.shared.u64 t, %1; cvt.u32.u64 %0, t; }"
        : "=r"(a) : "l"(p));
    return a;
}

__device__ __forceinline__ uint32_t lds32(uint32_t addr) {
    uint32_t v;
    asm volatile("ld.shared.b32 %0, [%1];" : "=r"(v) : "r"(addr));
    return v;
}

__device__ __forceinline__ void cp16(uint32_t dst, const void* src) {
    asm volatile("cp.async.cg.shared.global [%0], [%1], 16;"
                 :: "r"(dst), "l"(src) : "memory");
}
#define CP_COMMIT() asm volatile("cp.async.commit_group;" ::: "memory")
#define CP_WAIT_ALL() asm volatile("cp.async.wait_group 0;" ::: "memory")

#define MMA_BF16(d, a, b0, b1)                                              \
    asm volatile("mma.sync.aligned.m16n8k16.row.col.f32.bf16.bf16.f32 "     \
        "{%0,%1,%2,%3}, {%4,%5,%6,%7}, {%8,%9}, {%0,%1,%2,%3};"             \
        : "+f"((d)[0]), "+f"((d)[1]), "+f"((d)[2]), "+f"((d)[3])            \
        : "r"((a)[0]), "r"((a)[1]), "r"((a)[2]), "r"((a)[3]),               \
          "r"(b0), "r"(b1))

__device__ __forceinline__ uint32_t pack2(__nv_bfloat16 a, __nv_bfloat16 b) {
    __nv_bfloat162 v;
    v.x = a; v.y = b;
    return *reinterpret_cast<uint32_t*>(&v);
}

// ---------------- degree / norm / CSR / batch prep ----------------
__global__ void deg_kernel(const int* __restrict__ ei, int E) {
    int e = blockIdx.x * blockDim.x + threadIdx.x;
    if (e < E) atomicAdd(&g_degi[ei[E + e]], 1);
}

__global__ void dis_kernel(int n) {
    int i = blockIdx.x * blockDim.x + threadIdx.x;
    if (i < n) g_dis[i] = rsqrtf(1.0f + (float)g_degi[i]);
}

__global__ void scan1_kernel(int n) {
    __shared__ int sh[256];
    int t = threadIdx.x;
    int i = blockIdx.x * 256 + t;
    int v = (i < n) ? g_degi[i] : 0;
    sh[t] = v;
    __syncthreads();
#pragma unroll
    for (int off = 1; off < 256; off <<= 1) {
        int x = (t >= off) ? sh[t - off] : 0;
        __syncthreads();
        sh[t] += x;
        __syncthreads();
    }
    if (i < n) g_rowstart[i] = sh[t] - v;
    if (t == 255) g_bsum[blockIdx.x] = sh[255];
}

__global__ void scan2_kernel(int nb, int n) {
    __shared__ int sh[256];
    int t = threadIdx.x;
    int v = (t < nb) ? g_bsum[t] : 0;
    sh[t] = v;
    __syncthreads();
#pragma unroll
    for (int off = 1; off < 256; off <<= 1) {
        int x = (t >= off) ? sh[t - off] : 0;
        __syncthreads();
        sh[t] += x;
        __syncthreads();
    }
    if (t < nb) g_boff[t] = sh[t] - v;
    if (t == 255) g_rowstart[n] = sh[255];
}

__global__ void scan3_kernel(int n) {
    int i = blockIdx.x * 256 + threadIdx.x;
    if (i < n) {
        int r = g_rowstart[i] + g_boff[blockIdx.x];
        g_rowstart[i] = r;
        g_cursor[i] = r;
    }
}

__global__ void fill_kernel(const int* __restrict__ ei, int E) {
    int e = blockIdx.x * blockDim.x + threadIdx.x;
    if (e < E) {
        int dst = ei[E + e];
        int p = atomicAdd(&g_cursor[dst], 1);
        g_csr[p] = ei[e];
    }
}

__global__ void count_kernel(const int* __restrict__ bi, int n) {
    int i = blockIdx.x * blockDim.x + threadIdx.x;
    if (i < n) atomicAdd(&g_cnt[bi[i]], 1);
}

__global__ void gscan_kernel() {
    if (threadIdx.x == 0) {
        int s = 0;
        for (int g = 0; g < GG; g++) { g_start[g] = s; s += g_cnt[g]; }
    }
}

// ---------------- fp32 -> bf16 hi/lo split kernels ----------------
__global__ void conv_x_kernel(const float* __restrict__ x, int n4) {
    int i = blockIdx.x * blockDim.x + threadIdx.x;
    if (i >= n4) return;
    float4 a = reinterpret_cast<const float4*>(x)[i];
    __nv_bfloat16 h0 = __float2bfloat16(a.x), h1 = __float2bfloat16(a.y),
                  h2 = __float2bfloat16(a.z), h3 = __float2bfloat16(a.w);
    __nv_bfloat16 l0 = __float2bfloat16(a.x - __bfloat162float(h0));
    __nv_bfloat16 l1 = __float2bfloat16(a.y - __bfloat162float(h1));
    __nv_bfloat16 l2 = __float2bfloat16(a.z - __bfloat162float(h2));
    __nv_bfloat16 l3 = __float2bfloat16(a.w - __bfloat162float(h3));
    reinterpret_cast<uint2*>(g_Ahi)[i] = make_uint2(pack2(h0, h1), pack2(h2, h3));
    reinterpret_cast<uint2*>(g_Alo)[i] = make_uint2(pack2(l0, l1), pack2(l2, l3));
}

// W [KD][256] -> transposed hi/lo splits Wt [256][KD]
__global__ void conv_w_kernel(const float* __restrict__ W, int KD) {
    int i = blockIdx.x * blockDim.x + threadIdx.x;
    if (i >= KD * 256) return;
    int k = i >> 8;
    int n = i & 255;
    float w = W[i];
    __nv_bfloat16 h = __float2bfloat16(w);
    g_Wthi[(size_t)n * KD + k] = h;
    g_Wtlo[(size_t)n * KD + k] = __float2bfloat16(w - __bfloat162float(h));
}

// ---------------- bf16 split-GEMM via mma.sync: g_hs = dis * (A @ W) --------
// CTA: 128(M) x 128(N), 8 warps 4x2, warp tile 32x64 of m16n8k16 tiles.
// smem: double-buffered {Ahi, Alo, Bhi, Blo}, each [128 rows][16 k] bf16,
// row stride padded to 48 bytes. cp.async staging.
#define ARR_BYTES 6144              // 128 * 48
#define BUF_BYTES (4 * ARR_BYTES)   // 24576
#define SM_TOTAL  (2 * BUF_BYTES)   // 49152 = 48KB

template<int KD>
__global__ void __launch_bounds__(256) gemm_mma(int M) {
    extern __shared__ char smc[];
    const uint32_t sb = smem_u32(smc);
    const int t    = threadIdx.x;
    const int lane = t & 31;
    const int w    = t >> 5;
    const int wm   = w & 3;
    const int wn   = w >> 2;
    const int m0   = blockIdx.y * 128;
    const int n0   = blockIdx.x * 128;

    const int g  = lane >> 2;          // fragment row group
    const int qp = (lane & 3) * 4;     // byte offset of k-pair within row

    float acc[2][8][4];
#pragma unroll
    for (int mt = 0; mt < 2; mt++)
#pragma unroll
        for (int nt = 0; nt < 8; nt++)
#pragma unroll
            for (int q = 0; q < 4; q++) acc[mt][nt][q] = 0.0f;

    // staging: 4 arrays x 128 rows x 2 halves of 16B = 1024 chunks; 4/thread
    auto stage = [&](int c, int buf) {
#pragma unroll
        for (int j = 0; j < 4; j++) {
            int idx  = t * 4 + j;
            int arr  = idx >> 8;       // 0=Ahi 1=Alo 2=Bhi 3=Blo
            int rem  = idx & 255;
            int row  = rem >> 1;
            int half = rem & 1;
            const __nv_bfloat16* src;
            if (arr == 0)      src = g_Ahi  + (size_t)(m0 + row) * KD;
            else if (arr == 1) src = g_Alo  + (size_t)(m0 + row) * KD;
            else if (arr == 2) src = g_Wthi + (size_t)(n0 + row) * KD;
            else               src = g_Wtlo + (size_t)(n0 + row) * KD;
            src += c * 16 + half * 8;
            uint32_t dst = sb + buf * BUF_BYTES + arr * ARR_BYTES + row * 48 + half * 16;
            cp16(dst, src);
        }
        CP_COMMIT();
    };

    stage(0, 0);
    const int NCH = KD / 16;
    int buf = 0;
    for (int c = 0; c < NCH; c++) {
        CP_WAIT_ALL();
        __syncthreads();
        if (c + 1 < NCH) stage(c + 1, buf ^ 1);

        const uint32_t sAh = sb + buf * BUF_BYTES + (wm * 32) * 48;
        const uint32_t sAl = sAh + ARR_BYTES;
        const uint32_t sBh = sb + buf * BUF_BYTES + 2 * ARR_BYTES + (wn * 64) * 48;
        const uint32_t sBl = sBh + ARR_BYTES;

        uint32_t ahi[2][4], alo[2][4];
#pragma unroll
        for (int mt = 0; mt < 2; mt++) {
            uint32_t ao = sAh + mt * (16 * 48) + g * 48 + qp;
            ahi[mt][0] = lds32(ao);
            ahi[mt][1] = lds32(ao + 8 * 48);
            ahi[mt][2] = lds32(ao + 16);
            ahi[mt][3] = lds32(ao + 8 * 48 + 16);
            uint32_t al = sAl + mt * (16 * 48) + g * 48 + qp;
            alo[mt][0] = lds32(al);
            alo[mt][1] = lds32(al + 8 * 48);
            alo[mt][2] = lds32(al + 16);
            alo[mt][3] = lds32(al + 8 * 48 + 16);
        }
#pragma unroll
        for (int nt = 0; nt < 8; nt++) {
            uint32_t bo  = sBh + nt * (8 * 48) + g * 48 + qp;
            uint32_t bh0 = lds32(bo);
            uint32_t bh1 = lds32(bo + 16);
            uint32_t bl  = sBl + nt * (8 * 48) + g * 48 + qp;
            uint32_t bl0 = lds32(bl);
            uint32_t bl1 = lds32(bl + 16);
#pragma unroll
            for (int mt = 0; mt < 2; mt++) {
                MMA_BF16(acc[mt][nt], ahi[mt], bh0, bh1);
                MMA_BF16(acc[mt][nt], ahi[mt], bl0, bl1);
                MMA_BF16(acc[mt][nt], alo[mt], bh0, bh1);
            }
        }
        buf ^= 1;
    }

    // epilogue: scale by dis, write fp32 hs
    float* out = (float*)g_hs4;
#pragma unroll
    for (int mt = 0; mt < 2; mt++) {
        int r0 = m0 + wm * 32 + mt * 16 + g;
        int r1 = r0 + 8;
        float d0 = (r0 < M) ? g_dis[r0] : 0.0f;
        float d1 = (r1 < M) ? g_dis[r1] : 0.0f;
#pragma unroll
        for (int nt = 0; nt < 8; nt++) {
            int nc = n0 + wn * 64 + nt * 8 + (lane & 3) * 2;
            if (r0 < M)
                *reinterpret_cast<float2*>(out + (size_t)r0 * DD + nc) =
                    make_float2(acc[mt][nt][0] * d0, acc[mt][nt][1] * d0);
            if (r1 < M)
                *reinterpret_cast<float2*>(out + (size_t)r1 * DD + nc) =
                    make_float2(acc[mt][nt][2] * d1, acc[mt][nt][3] * d1);
        }
    }
}

// ---------------- fused CSR aggregate + tanh + bf16 split for next layer ------
__global__ void __launch_bounds__(256) aggregate_kernel(const float* __restrict__ bias,
                                                        int n) {
    int node = blockIdx.x * 4 + (threadIdx.x >> 6);
    int f4   = threadIdx.x & 63;
    if (node >= n) return;

    int s = g_rowstart[node];
    int e = g_rowstart[node + 1];

    float4 acc = g_hs4[(size_t)node * 64 + f4];  // self contribution

    int i = s;
    for (; i + 4 <= e; i += 4) {
        int s0 = __ldg(&g_csr[i]);
        int s1 = __ldg(&g_csr[i + 1]);
        int s2 = __ldg(&g_csr[i + 2]);
        int s3 = __ldg(&g_csr[i + 3]);
        float4 v0 = __ldg(&g_hs4[(size_t)s0 * 64 + f4]);
        float4 v1 = __ldg(&g_hs4[(size_t)s1 * 64 + f4]);
        float4 v2 = __ldg(&g_hs4[(size_t)s2 * 64 + f4]);
        float4 v3 = __ldg(&g_hs4[(size_t)s3 * 64 + f4]);
        acc.x += (v0.x + v1.x) + (v2.x + v3.x);
        acc.y += (v0.y + v1.y) + (v2.y + v3.y);
        acc.z += (v0.z + v1.z) + (v2.z + v3.z);
        acc.w += (v0.w + v1.w) + (v2.w + v3.w);
    }
    for (; i < e; i++) {
        int s0 = __ldg(&g_csr[i]);
        float4 v = __ldg(&g_hs4[(size_t)s0 * 64 + f4]);
        acc.x += v.x; acc.y += v.y; acc.z += v.z; acc.w += v.w;
    }

    float d = g_dis[node];
    float4 bv = reinterpret_cast<const float4*>(bias)[f4];
    float4 o;
    o.x = tanhf(fmaf(d, acc.x, bv.x));
    o.y = tanhf(fmaf(d, acc.y, bv.y));
    o.z = tanhf(fmaf(d, acc.z, bv.z));
    o.w = tanhf(fmaf(d, acc.w, bv.w));
    g_act4[(size_t)node * 64 + f4] = o;

    // bf16 hi/lo split for next layer's GEMM input
    __nv_bfloat16 h0 = __float2bfloat16(o.x), h1 = __float2bfloat16(o.y),
                  h2 = __float2bfloat16(o.z), h3 = __float2bfloat16(o.w);
    __nv_bfloat16 l0 = __float2bfloat16(o.x - __bfloat162float(h0));
    __nv_bfloat16 l1 = __float2bfloat16(o.y - __bfloat162float(h1));
    __nv_bfloat16 l2 = __float2bfloat16(o.z - __bfloat162float(h2));
    __nv_bfloat16 l3 = __float2bfloat16(o.w - __bfloat162float(h3));
    reinterpret_cast<uint2*>(g_Ahi)[(size_t)node * 64 + f4] =
        make_uint2(pack2(h0, h1), pack2(h2, h3));
    reinterpret_cast<uint2*>(g_Alo)[(size_t)node * 64 + f4] =
        make_uint2(pack2(l0, l1), pack2(l2, l3));
}

// ---------------- per-graph max + mean pooling ----------------
__global__ void pool_kernel() {
    int g = blockIdx.x;
    int f = threadIdx.x;
    int s = g_start[g];
    int c = g_cnt[g];
    const float* act = (const float*)g_act4;
    float mx = -INFINITY, sm = 0.f;
    for (int r = 0; r < c; r++) {
        float v = act[(size_t)(s + r) * DD + f];
        mx = fmaxf(mx, v);
        sm += v;
    }
    g_pool[g * (2 * DD) + f]      = mx;
    g_pool[g * (2 * DD) + DD + f] = sm / fmaxf((float)c, 1.0f);
}

// ---------------- tiny MLP ----------------
template<bool RELU>
__global__ void mlp_kernel(const float* __restrict__ A, const float* __restrict__ W,
                           const float* __restrict__ bias, float* __restrict__ C,
                           int K, int Nc) {
    __shared__ float sA[512];
    int row = blockIdx.x;
    for (int k = threadIdx.x; k < K; k += blockDim.x) sA[k] = A[(size_t)row * K + k];
    __syncthreads();
    for (int n = threadIdx.x; n < Nc; n += blockDim.x) {
        float acc = bias[n];
        for (int k = 0; k < K; k++) acc = fmaf(sA[k], W[(size_t)k * Nc + n], acc);
        C[(size_t)row * Nc + n] = RELU ? fmaxf(acc, 0.f) : acc;
    }
}

// ---------------- launch ----------------
extern "C" void kernel_launch(void* const* d_in, const int* in_sizes, int n_in,
                              void* d_out, int out_size) {
    const float* x   = (const float*)d_in[0];
    const int*   ei  = (const int*)d_in[1];
    const int*   bi  = (const int*)d_in[2];
    const float* W0 = (const float*)d_in[3];  const float* b0 = (const float*)d_in[4];
    const float* W1 = (const float*)d_in[5];  const float* b1 = (const float*)d_in[6];
    const float* W2 = (const float*)d_in[7];  const float* b2 = (const float*)d_in[8];
    const float* W3 = (const float*)d_in[9];  const float* b3 = (const float*)d_in[10];
    const float* fc1w = (const float*)d_in[11]; const float* fc1b = (const float*)d_in[12];
    const float* fc2w = (const float*)d_in[13]; const float* fc2b = (const float*)d_in[14];
    const float* ow   = (const float*)d_in[15]; const float* ob   = (const float*)d_in[16];

    const int F = 128;
    int N = in_sizes[0] / F;
    int E = in_sizes[1] / 2;
    int NB = (N + 255) / 256;

    void *p_degi, *p_cnt, *p_pool, *p_m1, *p_m2;
    cudaGetSymbolAddress(&p_degi, g_degi);
    cudaGetSymbolAddress(&p_cnt,  g_cnt);
    cudaGetSymbolAddress(&p_pool, g_pool);
    cudaGetSymbolAddress(&p_m1,   g_m1);
    cudaGetSymbolAddress(&p_m2,   g_m2);

    cudaMemsetAsync(p_degi, 0, (size_t)N * sizeof(int), 0);
    cudaMemsetAsync(p_cnt, 0, GG * sizeof(int), 0);

    deg_kernel<<<(E + 255) / 256, 256>>>(ei, E);
    dis_kernel<<<NB, 256>>>(N);
    scan1_kernel<<<NB, 256>>>(N);
    scan2_kernel<<<1, 256>>>(NB, N);
    scan3_kernel<<<NB, 256>>>(N);
    fill_kernel<<<(E + 255) / 256, 256>>>(ei, E);
    count_kernel<<<NB, 256>>>(bi, N);
    gscan_kernel<<<1, 32>>>();

    // layer-0 input split
    conv_x_kernel<<<(N * 32 + 255) / 256, 256>>>(x, N * 32);

    dim3 ggrid(2, (N + 127) / 128);
    int ablocks = (N + 3) / 4;

    const float* Ws[4] = {W0, W1, W2, W3};
    const float* bs[4] = {b0, b1, b2, b3};
    for (int layer = 0; layer < 4; layer++) {
        int KD = (layer == 0) ? 128 : 256;
        conv_w_kernel<<<(KD * 256 + 255) / 256, 256>>>(Ws[layer], KD);
        if (layer == 0) gemm_mma<128><<<ggrid, 256, SM_TOTAL>>>(N);
        else            gemm_mma<256><<<ggrid, 256, SM_TOTAL>>>(N);
        aggregate_kernel<<<ablocks, 256>>>(bs[layer], N);
    }

    pool_kernel<<<GG, DD>>>();
    mlp_kernel<true ><<<GG, 256>>>((const float*)p_pool, fc1w, fc1b, (float*)p_m1, 2 * DD, 512);
    mlp_kernel<true ><<<GG, 256>>>((const float*)p_m1,   fc2w, fc2b, (float*)p_m2, 512, 256);
    mlp_kernel<false><<<GG, 32 >>>((const float*)p_m2,   ow,   ob,   (float*)d_out, 256, 10);
}

// round 6
// speedup vs baseline: 2.2783x; 1.1532x over previous
#include <cuda_runtime.h>
#include <cuda_bf16.h>
#include <cstdint>
#include <math.h>

#define NN 50000
#define EE 1600000
#define DD 256
#define GG 64

// ---------------- static device scratch ----------------
__device__ float4 g_hs4[NN * DD / 4];   // hs = dis * (A @ W)  (fp32)
__device__ float4 g_act4[NN * DD / 4];  // layer activation (tanh output, fp32)
__device__ __nv_bfloat16 g_Ahi[(NN + 128) * DD];  // bf16 hi split of GEMM input A
__device__ __nv_bfloat16 g_Alo[(NN + 128) * DD];  // bf16 lo residual
__device__ __nv_bfloat16 g_Wthi[DD * DD];         // W^T hi  [n][k]
__device__ __nv_bfloat16 g_Wtlo[DD * DD];         // W^T lo  [n][k]
__device__ float  g_dis[NN];
__device__ int    g_degi[NN];
__device__ int    g_rowstart[NN + 1];
__device__ int    g_cursor[NN];
__device__ int    g_bsum[256];
__device__ int    g_boff[256];
__device__ int    g_csr[EE];
__device__ int    g_cnt[GG];
__device__ int    g_start[GG];
__device__ float  g_pool[GG * 2 * DD];
__device__ float  g_m1[GG * 512];
__device__ float  g_m2[GG * 256];

// ---------------- small helpers ----------------
__device__ __forceinline__ uint32_t smem_u32(const void* p) {
    uint32_t a;
    asm("{ .reg .u64 t; cvta.to.shared.u64 t, %1; cvt.u32.u64 %0, t; }"
        : "=r"(a) : "l"(p));
    return a;
}

__device__ __forceinline__ void cp16(uint32_t dst, const void* src) {
    asm volatile("cp.async.cg.shared.global [%0], [%1], 16;"
                 :: "r"(dst), "l"(src) : "memory");
}
#define CP_COMMIT() asm volatile("cp.async.commit_group;" ::: "memory")

#define LDMX4(r, addr)                                                      \
    asm volatile("ldmatrix.sync.aligned.m8n8.x4.shared.b16 "                \
        "{%0,%1,%2,%3}, [%4];"                                              \
        : "=r"((r)[0]), "=r"((r)[1]), "=r"((r)[2]), "=r"((r)[3])            \
        : "r"(addr))

#define MMA_BF16(d, a, b0, b1)                                              \
    asm volatile("mma.sync.aligned.m16n8k16.row.col.f32.bf16.bf16.f32 "     \
        "{%0,%1,%2,%3}, {%4,%5,%6,%7}, {%8,%9}, {%0,%1,%2,%3};"             \
        : "+f"((d)[0]), "+f"((d)[1]), "+f"((d)[2]), "+f"((d)[3])            \
        : "r"((a)[0]), "r"((a)[1]), "r"((a)[2]), "r"((a)[3]),               \
          "r"(b0), "r"(b1))

__device__ __forceinline__ uint32_t pack2(__nv_bfloat16 a, __nv_bfloat16 b) {
    __nv_bfloat162 v;
    v.x = a; v.y = b;
    return *reinterpret_cast<uint32_t*>(&v);
}

// ---------------- degree / norm / CSR / batch prep ----------------
__global__ void deg_kernel(const int* __restrict__ ei, int E) {
    int e = blockIdx.x * blockDim.x + threadIdx.x;
    if (e < E) atomicAdd(&g_degi[ei[E + e]], 1);
}

__global__ void dis_kernel(int n) {
    int i = blockIdx.x * blockDim.x + threadIdx.x;
    if (i < n) g_dis[i] = rsqrtf(1.0f + (float)g_degi[i]);
}

__global__ void scan1_kernel(int n) {
    __shared__ int sh[256];
    int t = threadIdx.x;
    int i = blockIdx.x * 256 + t;
    int v = (i < n) ? g_degi[i] : 0;
    sh[t] = v;
    __syncthreads();
#pragma unroll
    for (int off = 1; off < 256; off <<= 1) {
        int x = (t >= off) ? sh[t - off] : 0;
        __syncthreads();
        sh[t] += x;
        __syncthreads();
    }
    if (i < n) g_rowstart[i] = sh[t] - v;
    if (t == 255) g_bsum[blockIdx.x] = sh[255];
}

__global__ void scan2_kernel(int nb, int n) {
    __shared__ int sh[256];
    int t = threadIdx.x;
    int v = (t < nb) ? g_bsum[t] : 0;
    sh[t] = v;
    __syncthreads();
#pragma unroll
    for (int off = 1; off < 256; off <<= 1) {
        int x = (t >= off) ? sh[t - off] : 0;
        __syncthreads();
        sh[t] += x;
        __syncthreads();
    }
    if (t < nb) g_boff[t] = sh[t] - v;
    if (t == 255) g_rowstart[n] = sh[255];
}

__global__ void scan3_kernel(int n) {
    int i = blockIdx.x * 256 + threadIdx.x;
    if (i < n) {
        int r = g_rowstart[i] + g_boff[blockIdx.x];
        g_rowstart[i] = r;
        g_cursor[i] = r;
    }
}

__global__ void fill_kernel(const int* __restrict__ ei, int E) {
    int e = blockIdx.x * blockDim.x + threadIdx.x;
    if (e < E) {
        int dst = ei[E + e];
        int p = atomicAdd(&g_cursor[dst], 1);
        g_csr[p] = ei[e];
    }
}

__global__ void count_kernel(const int* __restrict__ bi, int n) {
    int i = blockIdx.x * blockDim.x + threadIdx.x;
    if (i < n) atomicAdd(&g_cnt[bi[i]], 1);
}

__global__ void gscan_kernel() {
    if (threadIdx.x == 0) {
        int s = 0;
        for (int g = 0; g < GG; g++) { g_start[g] = s; s += g_cnt[g]; }
    }
}

// ---------------- fp32 -> bf16 hi/lo split kernels ----------------
__global__ void conv_x_kernel(const float* __restrict__ x, int n4) {
    int i = blockIdx.x * blockDim.x + threadIdx.x;
    if (i >= n4) return;
    float4 a = reinterpret_cast<const float4*>(x)[i];
    __nv_bfloat16 h0 = __float2bfloat16(a.x), h1 = __float2bfloat16(a.y),
                  h2 = __float2bfloat16(a.z), h3 = __float2bfloat16(a.w);
    __nv_bfloat16 l0 = __float2bfloat16(a.x - __bfloat162float(h0));
    __nv_bfloat16 l1 = __float2bfloat16(a.y - __bfloat162float(h1));
    __nv_bfloat16 l2 = __float2bfloat16(a.z - __bfloat162float(h2));
    __nv_bfloat16 l3 = __float2bfloat16(a.w - __bfloat162float(h3));
    reinterpret_cast<uint2*>(g_Ahi)[i] = make_uint2(pack2(h0, h1), pack2(h2, h3));
    reinterpret_cast<uint2*>(g_Alo)[i] = make_uint2(pack2(l0, l1), pack2(l2, l3));
}

// W [KD][256] -> transposed hi/lo splits Wt [256][KD]
__global__ void conv_w_kernel(const float* __restrict__ W, int KD) {
    int i = blockIdx.x * blockDim.x + threadIdx.x;
    if (i >= KD * 256) return;
    int k = i >> 8;
    int n = i & 255;
    float w = W[i];
    __nv_bfloat16 h = __float2bfloat16(w);
    g_Wthi[(size_t)n * KD + k] = h;
    g_Wtlo[(size_t)n * KD + k] = __float2bfloat16(w - __bfloat162float(h));
}

// ---------------- bf16 split-GEMM via mma.sync + ldmatrix + 3-stage cp.async --
// CTA: 128(M) x 128(N), 8 warps 4x2, warp tile 32x64.
// Stage = 16-k chunk: 4 arrays {Ahi,Alo,Bhi,Blo} x [128 rows][16 k] bf16 (32B rows),
// XOR-swizzled (cc ^= (row>>2)&1) for conflict-free ldmatrix. 3 stages = 48KB.
#define ARRB 4096               // 128 rows * 32B
#define STGB (4 * ARRB)         // 16384
#define SM_TOTAL (3 * STGB)     // 49152

template<int KD>
__global__ void __launch_bounds__(256) gemm_mma(int M) {
    extern __shared__ char smc[];
    const uint32_t sb = smem_u32(smc);
    const int t    = threadIdx.x;
    const int lane = t & 31;
    const int w    = t >> 5;
    const int wm   = w & 3;
    const int wn   = w >> 2;
    const int m0   = blockIdx.y * 128;
    const int n0   = blockIdx.x * 128;

    float acc[2][8][4];
#pragma unroll
    for (int mt = 0; mt < 2; mt++)
#pragma unroll
        for (int nt = 0; nt < 8; nt++)
#pragma unroll
            for (int q = 0; q < 4; q++) acc[mt][nt][q] = 0.0f;

    // stage one 16-k chunk: 1024 x 16B cp.async chunks, 4 per thread
    auto stage = [&](int c, int buf) {
#pragma unroll
        for (int j = 0; j < 4; j++) {
            int idx = t * 4 + j;
            int arr = idx >> 8;       // 0=Ahi 1=Alo 2=Bhi 3=Blo
            int rem = idx & 255;
            int row = rem >> 1;
            int cc  = rem & 1;
            const __nv_bfloat16* src;
            int gr;
            if (arr == 0)      { src = g_Ahi;  gr = m0 + row; }
            else if (arr == 1) { src = g_Alo;  gr = m0 + row; }
            else if (arr == 2) { src = g_Wthi; gr = n0 + row; }
            else               { src = g_Wtlo; gr = n0 + row; }
            src += (size_t)gr * KD + c * 16 + cc * 8;
            uint32_t dst = sb + buf * STGB + arr * ARRB + row * 32 +
                           ((cc ^ ((row >> 2) & 1)) << 4);
            cp16(dst, src);
        }
        CP_COMMIT();
    };

    stage(0, 0);
    stage(1, 1);

    const int NCH = KD / 16;
    const int lr  = lane & 7;
    const int grp = lane >> 3;

    for (int c = 0; c < NCH; c++) {
        asm volatile("cp.async.wait_group 1;" ::: "memory");
        __syncthreads();
        int buf = c % 3;
        uint32_t sA = sb + buf * STGB;
        uint32_t sB = sA + 2 * ARRB;

        // A fragments (hi+lo) via ldmatrix.x4
        uint32_t ahi[2][4], alo[2][4];
#pragma unroll
        for (int mt = 0; mt < 2; mt++) {
            int row = wm * 32 + mt * 16 + lr + ((grp & 1) << 3);
            int cc  = grp >> 1;
            uint32_t off = row * 32 + ((cc ^ ((row >> 2) & 1)) << 4);
            LDMX4(ahi[mt], sA + off);
            LDMX4(alo[mt], sA + ARRB + off);
        }

        // prefetch next stage early (overlaps with MMA below)
        if (c + 2 < NCH) stage(c + 2, (c + 2) % 3);

        // B fragments + MMA
#pragma unroll
        for (int ntp = 0; ntp < 4; ntp++) {
            int row = wn * 64 + ntp * 16 + lr + ((grp >> 1) << 3);
            int cc  = grp & 1;
            uint32_t off = row * 32 + ((cc ^ ((row >> 2) & 1)) << 4);
            uint32_t bh[4], bl[4];
            LDMX4(bh, sB + off);
            LDMX4(bl, sB + ARRB + off);
#pragma unroll
            for (int mt = 0; mt < 2; mt++) {
                MMA_BF16(acc[mt][2 * ntp],     ahi[mt], bh[0], bh[1]);
                MMA_BF16(acc[mt][2 * ntp],     ahi[mt], bl[0], bl[1]);
                MMA_BF16(acc[mt][2 * ntp],     alo[mt], bh[0], bh[1]);
                MMA_BF16(acc[mt][2 * ntp + 1], ahi[mt], bh[2], bh[3]);
                MMA_BF16(acc[mt][2 * ntp + 1], ahi[mt], bl[2], bl[3]);
                MMA_BF16(acc[mt][2 * ntp + 1], alo[mt], bh[2], bh[3]);
            }
        }
    }

    // epilogue: scale by dis, write fp32 hs
    float* out = (float*)g_hs4;
#pragma unroll
    for (int mt = 0; mt < 2; mt++) {
        int r0 = m0 + wm * 32 + mt * 16 + (lane >> 2);
        int r1 = r0 + 8;
        float d0 = (r0 < M) ? g_dis[r0] : 0.0f;
        float d1 = (r1 < M) ? g_dis[r1] : 0.0f;
#pragma unroll
        for (int nt = 0; nt < 8; nt++) {
            int nc = n0 + wn * 64 + nt * 8 + (lane & 3) * 2;
            if (r0 < M)
                *reinterpret_cast<float2*>(out + (size_t)r0 * DD + nc) =
                    make_float2(acc[mt][nt][0] * d0, acc[mt][nt][1] * d0);
            if (r1 < M)
                *reinterpret_cast<float2*>(out + (size_t)r1 * DD + nc) =
                    make_float2(acc[mt][nt][2] * d1, acc[mt][nt][3] * d1);
        }
    }
}

// ---------------- fused CSR aggregate + tanh + bf16 split for next layer ------
__global__ void __launch_bounds__(256) aggregate_kernel(const float* __restrict__ bias,
                                                        int n) {
    int node = blockIdx.x * 4 + (threadIdx.x >> 6);
    int f4   = threadIdx.x & 63;
    if (node >= n) return;

    int s = g_rowstart[node];
    int e = g_rowstart[node + 1];

    float4 acc = g_hs4[(size_t)node * 64 + f4];  // self contribution

    int i = s;
    for (; i + 4 <= e; i += 4) {
        int s0 = __ldg(&g_csr[i]);
        int s1 = __ldg(&g_csr[i + 1]);
        int s2 = __ldg(&g_csr[i + 2]);
        int s3 = __ldg(&g_csr[i + 3]);
        float4 v0 = __ldg(&g_hs4[(size_t)s0 * 64 + f4]);
        float4 v1 = __ldg(&g_hs4[(size_t)s1 * 64 + f4]);
        float4 v2 = __ldg(&g_hs4[(size_t)s2 * 64 + f4]);
        float4 v3 = __ldg(&g_hs4[(size_t)s3 * 64 + f4]);
        acc.x += (v0.x + v1.x) + (v2.x + v3.x);
        acc.y += (v0.y + v1.y) + (v2.y + v3.y);
        acc.z += (v0.z + v1.z) + (v2.z + v3.z);
        acc.w += (v0.w + v1.w) + (v2.w + v3.w);
    }
    for (; i < e; i++) {
        int s0 = __ldg(&g_csr[i]);
        float4 v = __ldg(&g_hs4[(size_t)s0 * 64 + f4]);
        acc.x += v.x; acc.y += v.y; acc.z += v.z; acc.w += v.w;
    }

    float d = g_dis[node];
    float4 bv = reinterpret_cast<const float4*>(bias)[f4];
    float4 o;
    o.x = tanhf(fmaf(d, acc.x, bv.x));
    o.y = tanhf(fmaf(d, acc.y, bv.y));
    o.z = tanhf(fmaf(d, acc.z, bv.z));
    o.w = tanhf(fmaf(d, acc.w, bv.w));
    g_act4[(size_t)node * 64 + f4] = o;

    // bf16 hi/lo split for next layer's GEMM input
    __nv_bfloat16 h0 = __float2bfloat16(o.x), h1 = __float2bfloat16(o.y),
                  h2 = __float2bfloat16(o.z), h3 = __float2bfloat16(o.w);
    __nv_bfloat16 l0 = __float2bfloat16(o.x - __bfloat162float(h0));
    __nv_bfloat16 l1 = __float2bfloat16(o.y - __bfloat162float(h1));
    __nv_bfloat16 l2 = __float2bfloat16(o.z - __bfloat162float(h2));
    __nv_bfloat16 l3 = __float2bfloat16(o.w - __bfloat162float(h3));
    reinterpret_cast<uint2*>(g_Ahi)[(size_t)node * 64 + f4] =
        make_uint2(pack2(h0, h1), pack2(h2, h3));
    reinterpret_cast<uint2*>(g_Alo)[(size_t)node * 64 + f4] =
        make_uint2(pack2(l0, l1), pack2(l2, l3));
}

// ---------------- per-graph max + mean pooling ----------------
__global__ void pool_kernel() {
    int g = blockIdx.x;
    int f = threadIdx.x;
    int s = g_start[g];
    int c = g_cnt[g];
    const float* act = (const float*)g_act4;
    float mx = -INFINITY, sm = 0.f;
    for (int r = 0; r < c; r++) {
        float v = act[(size_t)(s + r) * DD + f];
        mx = fmaxf(mx, v);
        sm += v;
    }
    g_pool[g * (2 * DD) + f]      = mx;
    g_pool[g * (2 * DD) + DD + f] = sm / fmaxf((float)c, 1.0f);
}

// ---------------- tiny MLP ----------------
template<bool RELU>
__global__ void mlp_kernel(const float* __restrict__ A, const float* __restrict__ W,
                           const float* __restrict__ bias, float* __restrict__ C,
                           int K, int Nc) {
    __shared__ float sA[512];
    int row = blockIdx.x;
    for (int k = threadIdx.x; k < K; k += blockDim.x) sA[k] = A[(size_t)row * K + k];
    __syncthreads();
    for (int n = threadIdx.x; n < Nc; n += blockDim.x) {
        float acc = bias[n];
        for (int k = 0; k < K; k++) acc = fmaf(sA[k], W[(size_t)k * Nc + n], acc);
        C[(size_t)row * Nc + n] = RELU ? fmaxf(acc, 0.f) : acc;
    }
}

// ---------------- launch ----------------
extern "C" void kernel_launch(void* const* d_in, const int* in_sizes, int n_in,
                              void* d_out, int out_size) {
    const float* x   = (const float*)d_in[0];
    const int*   ei  = (const int*)d_in[1];
    const int*   bi  = (const int*)d_in[2];
    const float* W0 = (const float*)d_in[3];  const float* b0 = (const float*)d_in[4];
    const float* W1 = (const float*)d_in[5];  const float* b1 = (const float*)d_in[6];
    const float* W2 = (const float*)d_in[7];  const float* b2 = (const float*)d_in[8];
    const float* W3 = (const float*)d_in[9];  const float* b3 = (const float*)d_in[10];
    const float* fc1w = (const float*)d_in[11]; const float* fc1b = (const float*)d_in[12];
    const float* fc2w = (const float*)d_in[13]; const float* fc2b = (const float*)d_in[14];
    const float* ow   = (const float*)d_in[15]; const float* ob   = (const float*)d_in[16];

    const int F = 128;
    int N = in_sizes[0] / F;
    int E = in_sizes[1] / 2;
    int NB = (N + 255) / 256;

    void *p_degi, *p_cnt, *p_pool, *p_m1, *p_m2;
    cudaGetSymbolAddress(&p_degi, g_degi);
    cudaGetSymbolAddress(&p_cnt,  g_cnt);
    cudaGetSymbolAddress(&p_pool, g_pool);
    cudaGetSymbolAddress(&p_m1,   g_m1);
    cudaGetSymbolAddress(&p_m2,   g_m2);

    dim3 ggrid(2, (N + 127) / 128);
    int ablocks = (N + 3) / 4;

    // Launch order arranged so ncu (-s 5 -c 1) profiles gemm_mma at index 5:
    // 0:memset 1:deg 2:dis 3:conv_x 4:conv_w 5:gemm
    cudaMemsetAsync(p_degi, 0, (size_t)N * sizeof(int), 0);          // 0
    deg_kernel<<<(E + 255) / 256, 256>>>(ei, E);                     // 1
    dis_kernel<<<NB, 256>>>(N);                                      // 2
    conv_x_kernel<<<(N * 32 + 255) / 256, 256>>>(x, N * 32);         // 3
    conv_w_kernel<<<(128 * 256 + 255) / 256, 256>>>(W0, 128);        // 4
    gemm_mma<128><<<ggrid, 256, SM_TOTAL>>>(N);                      // 5 <- profiled

    // CSR build (needed only by aggregate)
    scan1_kernel<<<NB, 256>>>(N);
    scan2_kernel<<<1, 256>>>(NB, N);
    scan3_kernel<<<NB, 256>>>(N);
    fill_kernel<<<(E + 255) / 256, 256>>>(ei, E);

    // batch bookkeeping (needed only by pool)
    cudaMemsetAsync(p_cnt, 0, GG * sizeof(int), 0);
    count_kernel<<<NB, 256>>>(bi, N);
    gscan_kernel<<<1, 32>>>();

    aggregate_kernel<<<ablocks, 256>>>(b0, N);

    const float* Ws[4] = {W0, W1, W2, W3};
    const float* bs[4] = {b0, b1, b2, b3};
    for (int layer = 1; layer < 4; layer++) {
        conv_w_kernel<<<(256 * 256 + 255) / 256, 256>>>(Ws[layer], 256);
        gemm_mma<256><<<ggrid, 256, SM_TOTAL>>>(N);
        aggregate_kernel<<<ablocks, 256>>>(bs[layer], N);
    }

    pool_kernel<<<GG, DD>>>();
    mlp_kernel<true ><<<GG, 256>>>((const float*)p_pool, fc1w, fc1b, (float*)p_m1, 2 * DD, 512);
    mlp_kernel<true ><<<GG, 256>>>((const float*)p_m1,   fc2w, fc2b, (float*)p_m2, 512, 256);
    mlp_kernel<false><<<GG, 32 >>>((const float*)p_m2,   ow,   ob,   (float*)d_out, 256, 10);
}

// round 7
// speedup vs baseline: 2.6386x; 1.1582x over previous
#include <cuda_runtime.h>
#include <cuda_bf16.h>
#include <cuda_fp16.h>
#include <cstdint>
#include <math.h>

#define NN 50000
#define EE 1600000
#define DD 256
#define GG 64

// ---------------- static device scratch ----------------
__device__ float4 g_act4[NN * DD / 4];            // final activation (fp32, pooling)
__device__ __half g_xs16[(NN + 128) * DD];        // xs = dis*act (fp16 gather array)
__device__ __nv_bfloat16 g_Ahi[(NN + 128) * DD];  // bf16 hi split of GEMM input Y
__device__ __nv_bfloat16 g_Alo[(NN + 128) * DD];  // bf16 lo residual
__device__ __nv_bfloat16 g_Wthi[DD * DD];         // W^T hi  [n][k]
__device__ __nv_bfloat16 g_Wtlo[DD * DD];         // W^T lo  [n][k]
__device__ float  g_dis[NN];
__device__ int    g_degi[NN];
__device__ int    g_rowstart[NN + 1];
__device__ int    g_cursor[NN];
__device__ int    g_bsum[256];
__device__ int    g_boff[256];
__device__ int    g_csr[EE];
__device__ int    g_cnt[GG];
__device__ int    g_start[GG];
__device__ float  g_pool[GG * 2 * DD];
__device__ float  g_m1[GG * 512];
__device__ float  g_m2[GG * 256];

// ---------------- small helpers ----------------
__device__ __forceinline__ uint32_t smem_u32(const void* p) {
    uint32_t a;
    asm("{ .reg .u64 t; cvta.to.shared.u64 t, %1; cvt.u32.u64 %0, t; }"
        : "=r"(a) : "l"(p));
    return a;
}

__device__ __forceinline__ void cp16(uint32_t dst, const void* src) {
    asm volatile("cp.async.cg.shared.global [%0], [%1], 16;"
                 :: "r"(dst), "l"(src) : "memory");
}
#define CP_COMMIT() asm volatile("cp.async.commit_group;" ::: "memory")

#define LDMX4(r, addr)                                                      \
    asm volatile("ldmatrix.sync.aligned.m8n8.x4.shared.b16 "                \
        "{%0,%1,%2,%3}, [%4];"                                              \
        : "=r"((r)[0]), "=r"((r)[1]), "=r"((r)[2]), "=r"((r)[3])            \
        : "r"(addr))

#define MMA_BF16(d, a, b0, b1)                                              \
    asm volatile("mma.sync.aligned.m16n8k16.row.col.f32.bf16.bf16.f32 "     \
        "{%0,%1,%2,%3}, {%4,%5,%6,%7}, {%8,%9}, {%0,%1,%2,%3};"             \
        : "+f"((d)[0]), "+f"((d)[1]), "+f"((d)[2]), "+f"((d)[3])            \
        : "r"((a)[0]), "r"((a)[1]), "r"((a)[2]), "r"((a)[3]),               \
          "r"(b0), "r"(b1))

__device__ __forceinline__ uint32_t packbf2(__nv_bfloat16 a, __nv_bfloat16 b) {
    __nv_bfloat162 v;
    v.x = a; v.y = b;
    return *reinterpret_cast<uint32_t*>(&v);
}

// ---------------- degree / norm / CSR / batch prep ----------------
__global__ void deg_kernel(const int* __restrict__ ei, int E) {
    int e = blockIdx.x * blockDim.x + threadIdx.x;
    if (e < E) atomicAdd(&g_degi[ei[E + e]], 1);
}

__global__ void dis_kernel(int n) {
    int i = blockIdx.x * blockDim.x + threadIdx.x;
    if (i < n) g_dis[i] = rsqrtf(1.0f + (float)g_degi[i]);
}

__global__ void scan1_kernel(int n) {
    __shared__ int sh[256];
    int t = threadIdx.x;
    int i = blockIdx.x * 256 + t;
    int v = (i < n) ? g_degi[i] : 0;
    sh[t] = v;
    __syncthreads();
#pragma unroll
    for (int off = 1; off < 256; off <<= 1) {
        int x = (t >= off) ? sh[t - off] : 0;
        __syncthreads();
        sh[t] += x;
        __syncthreads();
    }
    if (i < n) g_rowstart[i] = sh[t] - v;
    if (t == 255) g_bsum[blockIdx.x] = sh[255];
}

__global__ void scan2_kernel(int nb, int n) {
    __shared__ int sh[256];
    int t = threadIdx.x;
    int v = (t < nb) ? g_bsum[t] : 0;
    sh[t] = v;
    __syncthreads();
#pragma unroll
    for (int off = 1; off < 256; off <<= 1) {
        int x = (t >= off) ? sh[t - off] : 0;
        __syncthreads();
        sh[t] += x;
        __syncthreads();
    }
    if (t < nb) g_boff[t] = sh[t] - v;
    if (t == 255) g_rowstart[n] = sh[255];
}

__global__ void scan3_kernel(int n) {
    int i = blockIdx.x * 256 + threadIdx.x;
    if (i < n) {
        int r = g_rowstart[i] + g_boff[blockIdx.x];
        g_rowstart[i] = r;
        g_cursor[i] = r;
    }
}

__global__ void fill_kernel(const int* __restrict__ ei, int E) {
    int e = blockIdx.x * blockDim.x + threadIdx.x;
    if (e < E) {
        int dst = ei[E + e];
        int p = atomicAdd(&g_cursor[dst], 1);
        g_csr[p] = ei[e];
    }
}

__global__ void count_kernel(const int* __restrict__ bi, int n) {
    int i = blockIdx.x * blockDim.x + threadIdx.x;
    if (i < n) atomicAdd(&g_cnt[bi[i]], 1);
}

__global__ void gscan_kernel() {
    if (threadIdx.x == 0) {
        int s = 0;
        for (int g = 0; g < GG; g++) { g_start[g] = s; s += g_cnt[g]; }
    }
}

// ---------------- xs0 = fp16(dis * x), x is [N,128] fp32 ----------------
__global__ void conv_x0_kernel(const float* __restrict__ x, int n) {
    int i = blockIdx.x * blockDim.x + threadIdx.x;  // over n*64 half2
    if (i >= n * 64) return;
    int node = i >> 6;
    float d = g_dis[node];
    float2 a = reinterpret_cast<const float2*>(x)[i];
    reinterpret_cast<__half2*>(g_xs16)[i] = __floats2half2_rn(d * a.x, d * a.y);
}

// W [KD][256] -> transposed hi/lo splits Wt [256][KD]
__global__ void conv_w_kernel(const float* __restrict__ W, int KD) {
    int i = blockIdx.x * blockDim.x + threadIdx.x;
    if (i >= KD * 256) return;
    int k = i >> 8;
    int n = i & 255;
    float w = W[i];
    __nv_bfloat16 h = __float2bfloat16(w);
    g_Wthi[(size_t)n * KD + k] = h;
    g_Wtlo[(size_t)n * KD + k] = __float2bfloat16(w - __bfloat162float(h));
}

// ---------------- CSR aggregate (fp16 gather, fp32 accum) --------------------
// Y[dst] = dis[dst] * (xs[dst] + sum_{src} xs[src]); write bf16 hi/lo splits.
// 64 threads per node, 4 nodes per 256-thread block.
template<int KD>
__global__ void __launch_bounds__(256) aggregate_kernel(int n) {
    int node = blockIdx.x * 4 + (threadIdx.x >> 6);
    int f    = threadIdx.x & 63;
    if (node >= n) return;

    int s = g_rowstart[node];
    int e = g_rowstart[node + 1];
    const char* xs = (const char*)g_xs16;
    constexpr size_t ROWB = KD * 2;

    if constexpr (KD == 256) {
        uint2 sv = __ldg((const uint2*)(xs + (size_t)node * ROWB) + f);
        float2 a0 = __half22float2(*(__half2*)&sv.x);
        float2 a1 = __half22float2(*(__half2*)&sv.y);
        int i = s;
        for (; i + 4 <= e; i += 4) {
            int s0 = __ldg(&g_csr[i]);
            int s1 = __ldg(&g_csr[i + 1]);
            int s2 = __ldg(&g_csr[i + 2]);
            int s3 = __ldg(&g_csr[i + 3]);
            uint2 v0 = __ldg((const uint2*)(xs + (size_t)s0 * ROWB) + f);
            uint2 v1 = __ldg((const uint2*)(xs + (size_t)s1 * ROWB) + f);
            uint2 v2 = __ldg((const uint2*)(xs + (size_t)s2 * ROWB) + f);
            uint2 v3 = __ldg((const uint2*)(xs + (size_t)s3 * ROWB) + f);
            float2 t;
            t = __half22float2(*(__half2*)&v0.x); a0.x += t.x; a0.y += t.y;
            t = __half22float2(*(__half2*)&v0.y); a1.x += t.x; a1.y += t.y;
            t = __half22float2(*(__half2*)&v1.x); a0.x += t.x; a0.y += t.y;
            t = __half22float2(*(__half2*)&v1.y); a1.x += t.x; a1.y += t.y;
            t = __half22float2(*(__half2*)&v2.x); a0.x += t.x; a0.y += t.y;
            t = __half22float2(*(__half2*)&v2.y); a1.x += t.x; a1.y += t.y;
            t = __half22float2(*(__half2*)&v3.x); a0.x += t.x; a0.y += t.y;
            t = __half22float2(*(__half2*)&v3.y); a1.x += t.x; a1.y += t.y;
        }
        for (; i < e; i++) {
            int s0 = __ldg(&g_csr[i]);
            uint2 v = __ldg((const uint2*)(xs + (size_t)s0 * ROWB) + f);
            float2 t;
            t = __half22float2(*(__half2*)&v.x); a0.x += t.x; a0.y += t.y;
            t = __half22float2(*(__half2*)&v.y); a1.x += t.x; a1.y += t.y;
        }
        float d = g_dis[node];
        float y0 = d * a0.x, y1 = d * a0.y, y2 = d * a1.x, y3 = d * a1.y;
        __nv_bfloat16 h0 = __float2bfloat16(y0), h1 = __float2bfloat16(y1),
                      h2 = __float2bfloat16(y2), h3 = __float2bfloat16(y3);
        __nv_bfloat16 l0 = __float2bfloat16(y0 - __bfloat162float(h0));
        __nv_bfloat16 l1 = __float2bfloat16(y1 - __bfloat162float(h1));
        __nv_bfloat16 l2 = __float2bfloat16(y2 - __bfloat162float(h2));
        __nv_bfloat16 l3 = __float2bfloat16(y3 - __bfloat162float(h3));
        reinterpret_cast<uint2*>(g_Ahi)[(size_t)node * 64 + f] =
            make_uint2(packbf2(h0, h1), packbf2(h2, h3));
        reinterpret_cast<uint2*>(g_Alo)[(size_t)node * 64 + f] =
            make_uint2(packbf2(l0, l1), packbf2(l2, l3));
    } else {  // KD == 128
        uint32_t sv = __ldg((const uint32_t*)(xs + (size_t)node * ROWB) + f);
        float2 a0 = __half22float2(*(__half2*)&sv);
        int i = s;
        for (; i + 4 <= e; i += 4) {
            int s0 = __ldg(&g_csr[i]);
            int s1 = __ldg(&g_csr[i + 1]);
            int s2 = __ldg(&g_csr[i + 2]);
            int s3 = __ldg(&g_csr[i + 3]);
            uint32_t v0 = __ldg((const uint32_t*)(xs + (size_t)s0 * ROWB) + f);
            uint32_t v1 = __ldg((const uint32_t*)(xs + (size_t)s1 * ROWB) + f);
            uint32_t v2 = __ldg((const uint32_t*)(xs + (size_t)s2 * ROWB) + f);
            uint32_t v3 = __ldg((const uint32_t*)(xs + (size_t)s3 * ROWB) + f);
            float2 t;
            t = __half22float2(*(__half2*)&v0); a0.x += t.x; a0.y += t.y;
            t = __half22float2(*(__half2*)&v1); a0.x += t.x; a0.y += t.y;
            t = __half22float2(*(__half2*)&v2); a0.x += t.x; a0.y += t.y;
            t = __half22float2(*(__half2*)&v3); a0.x += t.x; a0.y += t.y;
        }
        for (; i < e; i++) {
            int s0 = __ldg(&g_csr[i]);
            uint32_t v = __ldg((const uint32_t*)(xs + (size_t)s0 * ROWB) + f);
            float2 t = __half22float2(*(__half2*)&v);
            a0.x += t.x; a0.y += t.y;
        }
        float d = g_dis[node];
        float y0 = d * a0.x, y1 = d * a0.y;
        __nv_bfloat16 h0 = __float2bfloat16(y0), h1 = __float2bfloat16(y1);
        __nv_bfloat16 l0 = __float2bfloat16(y0 - __bfloat162float(h0));
        __nv_bfloat16 l1 = __float2bfloat16(y1 - __bfloat162float(h1));
        reinterpret_cast<uint32_t*>(g_Ahi)[(size_t)node * 64 + f] = packbf2(h0, h1);
        reinterpret_cast<uint32_t*>(g_Alo)[(size_t)node * 64 + f] = packbf2(l0, l1);
    }
}

// ---------------- bf16 split-GEMM (mma.sync + ldmatrix + 3-stage cp.async) ----
// z = Y @ W; act = tanh(z + b); xs16 = fp16(dis*act); LAST also writes act fp32.
#define ARRB 4096               // 128 rows * 32B
#define STGB (4 * ARRB)         // 16384
#define SM_TOTAL (3 * STGB)     // 49152

template<int KD, bool LAST>
__global__ void __launch_bounds__(256) gemm_mma(const float* __restrict__ bias, int M) {
    extern __shared__ char smc[];
    const uint32_t sb = smem_u32(smc);
    const int t    = threadIdx.x;
    const int lane = t & 31;
    const int w    = t >> 5;
    const int wm   = w & 3;
    const int wn   = w >> 2;
    const int m0   = blockIdx.y * 128;
    const int n0   = blockIdx.x * 128;

    float acc[2][8][4];
#pragma unroll
    for (int mt = 0; mt < 2; mt++)
#pragma unroll
        for (int nt = 0; nt < 8; nt++)
#pragma unroll
            for (int q = 0; q < 4; q++) acc[mt][nt][q] = 0.0f;

    auto stage = [&](int c, int buf) {
#pragma unroll
        for (int j = 0; j < 4; j++) {
            int idx = t * 4 + j;
            int arr = idx >> 8;       // 0=Ahi 1=Alo 2=Bhi 3=Blo
            int rem = idx & 255;
            int row = rem >> 1;
            int cc  = rem & 1;
            const __nv_bfloat16* src;
            int gr;
            if (arr == 0)      { src = g_Ahi;  gr = m0 + row; }
            else if (arr == 1) { src = g_Alo;  gr = m0 + row; }
            else if (arr == 2) { src = g_Wthi; gr = n0 + row; }
            else               { src = g_Wtlo; gr = n0 + row; }
            src += (size_t)gr * KD + c * 16 + cc * 8;
            uint32_t dst = sb + buf * STGB + arr * ARRB + row * 32 +
                           ((cc ^ ((row >> 2) & 1)) << 4);
            cp16(dst, src);
        }
        CP_COMMIT();
    };

    stage(0, 0);
    stage(1, 1);

    const int NCH = KD / 16;
    const int lr  = lane & 7;
    const int grp = lane >> 3;

    for (int c = 0; c < NCH; c++) {
        asm volatile("cp.async.wait_group 1;" ::: "memory");
        __syncthreads();
        int buf = c % 3;
        uint32_t sA = sb + buf * STGB;
        uint32_t sB = sA + 2 * ARRB;

        uint32_t ahi[2][4], alo[2][4];
#pragma unroll
        for (int mt = 0; mt < 2; mt++) {
            int row = wm * 32 + mt * 16 + lr + ((grp & 1) << 3);
            int cc  = grp >> 1;
            uint32_t off = row * 32 + ((cc ^ ((row >> 2) & 1)) << 4);
            LDMX4(ahi[mt], sA + off);
            LDMX4(alo[mt], sA + ARRB + off);
        }

        if (c + 2 < NCH) stage(c + 2, (c + 2) % 3);

#pragma unroll
        for (int ntp = 0; ntp < 4; ntp++) {
            int row = wn * 64 + ntp * 16 + lr + ((grp >> 1) << 3);
            int cc  = grp & 1;
            uint32_t off = row * 32 + ((cc ^ ((row >> 2) & 1)) << 4);
            uint32_t bh[4], bl[4];
            LDMX4(bh, sB + off);
            LDMX4(bl, sB + ARRB + off);
#pragma unroll
            for (int mt = 0; mt < 2; mt++) {
                MMA_BF16(acc[mt][2 * ntp],     ahi[mt], bh[0], bh[1]);
                MMA_BF16(acc[mt][2 * ntp],     ahi[mt], bl[0], bl[1]);
                MMA_BF16(acc[mt][2 * ntp],     alo[mt], bh[0], bh[1]);
                MMA_BF16(acc[mt][2 * ntp + 1], ahi[mt], bh[2], bh[3]);
                MMA_BF16(acc[mt][2 * ntp + 1], ahi[mt], bl[2], bl[3]);
                MMA_BF16(acc[mt][2 * ntp + 1], alo[mt], bh[2], bh[3]);
            }
        }
    }

    // epilogue: act = tanh(z + b); xs16 = fp16(dis*act); LAST: act fp32 for pool
    float* actout = (float*)g_act4;
#pragma unroll
    for (int mt = 0; mt < 2; mt++) {
        int r0 = m0 + wm * 32 + mt * 16 + (lane >> 2);
        int r1 = r0 + 8;
        float d0 = (r0 < M) ? g_dis[r0] : 0.0f;
        float d1 = (r1 < M) ? g_dis[r1] : 0.0f;
#pragma unroll
        for (int nt = 0; nt < 8; nt++) {
            int nc = n0 + wn * 64 + nt * 8 + (lane & 3) * 2;
            float b0 = __ldg(&bias[nc]);
            float b1 = __ldg(&bias[nc + 1]);
            if (r0 < M) {
                float t0 = tanhf(acc[mt][nt][0] + b0);
                float t1 = tanhf(acc[mt][nt][1] + b1);
                if (LAST) {
                    *reinterpret_cast<float2*>(actout + (size_t)r0 * DD + nc) =
                        make_float2(t0, t1);
                } else {
                    *reinterpret_cast<__half2*>(g_xs16 + (size_t)r0 * DD + nc) =
                        __floats2half2_rn(d0 * t0, d0 * t1);
                }
            }
            if (r1 < M) {
                float t2 = tanhf(acc[mt][nt][2] + b0);
                float t3 = tanhf(acc[mt][nt][3] + b1);
                if (LAST) {
                    *reinterpret_cast<float2*>(actout + (size_t)r1 * DD + nc) =
                        make_float2(t2, t3);
                } else {
                    *reinterpret_cast<__half2*>(g_xs16 + (size_t)r1 * DD + nc) =
                        __floats2half2_rn(d1 * t2, d1 * t3);
                }
            }
        }
    }
}

// ---------------- per-graph max + mean pooling ----------------
__global__ void pool_kernel() {
    int g = blockIdx.x;
    int f = threadIdx.x;
    int s = g_start[g];
    int c = g_cnt[g];
    const float* act = (const float*)g_act4;
    float mx = -INFINITY, sm = 0.f;
    for (int r = 0; r < c; r++) {
        float v = act[(size_t)(s + r) * DD + f];
        mx = fmaxf(mx, v);
        sm += v;
    }
    g_pool[g * (2 * DD) + f]      = mx;
    g_pool[g * (2 * DD) + DD + f] = sm / fmaxf((float)c, 1.0f);
}

// ---------------- tiny MLP ----------------
template<bool RELU>
__global__ void mlp_kernel(const float* __restrict__ A, const float* __restrict__ W,
                           const float* __restrict__ bias, float* __restrict__ C,
                           int K, int Nc) {
    __shared__ float sA[512];
    int row = blockIdx.x;
    for (int k = threadIdx.x; k < K; k += blockDim.x) sA[k] = A[(size_t)row * K + k];
    __syncthreads();
    for (int n = threadIdx.x; n < Nc; n += blockDim.x) {
        float acc = bias[n];
        for (int k = 0; k < K; k++) acc = fmaf(sA[k], W[(size_t)k * Nc + n], acc);
        C[(size_t)row * Nc + n] = RELU ? fmaxf(acc, 0.f) : acc;
    }
}

// ---------------- launch ----------------
extern "C" void kernel_launch(void* const* d_in, const int* in_sizes, int n_in,
                              void* d_out, int out_size) {
    const float* x   = (const float*)d_in[0];
    const int*   ei  = (const int*)d_in[1];
    const int*   bi  = (const int*)d_in[2];
    const float* W0 = (const float*)d_in[3];  const float* b0 = (const float*)d_in[4];
    const float* W1 = (const float*)d_in[5];  const float* b1 = (const float*)d_in[6];
    const float* W2 = (const float*)d_in[7];  const float* b2 = (const float*)d_in[8];
    const float* W3 = (const float*)d_in[9];  const float* b3 = (const float*)d_in[10];
    const float* fc1w = (const float*)d_in[11]; const float* fc1b = (const float*)d_in[12];
    const float* fc2w = (const float*)d_in[13]; const float* fc2b = (const float*)d_in[14];
    const float* ow   = (const float*)d_in[15]; const float* ob   = (const float*)d_in[16];

    const int F = 128;
    int N = in_sizes[0] / F;
    int E = in_sizes[1] / 2;
    int NB = (N + 255) / 256;

    void *p_degi, *p_cnt, *p_pool, *p_m1, *p_m2;
    cudaGetSymbolAddress(&p_degi, g_degi);
    cudaGetSymbolAddress(&p_cnt,  g_cnt);
    cudaGetSymbolAddress(&p_pool, g_pool);
    cudaGetSymbolAddress(&p_m1,   g_m1);
    cudaGetSymbolAddress(&p_m2,   g_m2);

    dim3 ggrid(2, (N + 127) / 128);
    int ablocks = (N + 3) / 4;

    // prep: degree, norm, CSR, batch bookkeeping
    cudaMemsetAsync(p_degi, 0, (size_t)N * sizeof(int), 0);
    cudaMemsetAsync(p_cnt, 0, GG * sizeof(int), 0);
    deg_kernel<<<(E + 255) / 256, 256>>>(ei, E);
    dis_kernel<<<NB, 256>>>(N);
    conv_x0_kernel<<<(N * 64 + 255) / 256, 256>>>(x, N);
    scan1_kernel<<<NB, 256>>>(N);
    scan2_kernel<<<1, 256>>>(NB, N);
    scan3_kernel<<<NB, 256>>>(N);
    fill_kernel<<<(E + 255) / 256, 256>>>(ei, E);
    count_kernel<<<NB, 256>>>(bi, N);
    gscan_kernel<<<1, 32>>>();

    // layer 0: aggregate X (128-dim), then GEMM with W0
    conv_w_kernel<<<(128 * 256 + 255) / 256, 256>>>(W0, 128);
    aggregate_kernel<128><<<ablocks, 256>>>(N);
    gemm_mma<128, false><<<ggrid, 256, SM_TOTAL>>>(b0, N);

    // layers 1-2
    conv_w_kernel<<<(256 * 256 + 255) / 256, 256>>>(W1, 256);
    aggregate_kernel<256><<<ablocks, 256>>>(N);
    gemm_mma<256, false><<<ggrid, 256, SM_TOTAL>>>(b1, N);

    conv_w_kernel<<<(256 * 256 + 255) / 256, 256>>>(W2, 256);
    aggregate_kernel<256><<<ablocks, 256>>>(N);
    gemm_mma<256, false><<<ggrid, 256, SM_TOTAL>>>(b2, N);

    // layer 3 (last): GEMM writes fp32 act for pooling
    conv_w_kernel<<<(256 * 256 + 255) / 256, 256>>>(W3, 256);
    aggregate_kernel<256><<<ablocks, 256>>>(N);
    gemm_mma<256, true><<<ggrid, 256, SM_TOTAL>>>(b3, N);

    pool_kernel<<<GG, DD>>>();
    mlp_kernel<true ><<<GG, 256>>>((const float*)p_pool, fc1w, fc1b, (float*)p_m1, 2 * DD, 512);
    mlp_kernel<true ><<<GG, 256>>>((const float*)p_m1,   fc2w, fc2b, (float*)p_m2, 512, 256);
    mlp_kernel<false><<<GG, 32 >>>((const float*)p_m2,   ow,   ob,   (float*)d_out, 256, 10);
}

// round 8
// speedup vs baseline: 3.0330x; 1.1495x over previous
#include <cuda_runtime.h>
#include <cuda_fp16.h>
#include <cstdint>
#include <math.h>

#define NN 50000
#define EE 1600000
#define DD 256
#define GG 64

// ---------------- static device scratch ----------------
__device__ float4 g_act4[NN * DD / 4];        // final activation (fp32, pooling)
__device__ __half g_xs16[(NN + 128) * DD];    // xs = dis*act (fp16 gather array)
__device__ __half g_Y16[(NN + 128) * DD];     // Y = GEMM input (fp16)
__device__ __half g_Wth[4 * DD * DD];         // per-layer W^T hi (fp16)  [n][k]
__device__ __half g_Wtl[4 * DD * DD];         // per-layer W^T lo residual (fp16)
__device__ float  g_dis[NN];
__device__ int    g_degi[NN];
__device__ int    g_total;
__device__ int    g_rowstart[NN];
__device__ int    g_rowend[NN];
__device__ int    g_cursor[NN];
__device__ int    g_csr[EE];
__device__ int    g_cnt[GG];
__device__ int    g_start[GG];
__device__ float  g_pool[GG * 2 * DD];
__device__ float  g_m1[GG * 512];
__device__ float  g_m2[GG * 256];

// ---------------- small helpers ----------------
__device__ __forceinline__ uint32_t smem_u32(const void* p) {
    uint32_t a;
    asm("{ .reg .u64 t; cvta.to.shared.u64 t, %1; cvt.u32.u64 %0, t; }"
        : "=r"(a) : "l"(p));
    return a;
}

__device__ __forceinline__ void cp16(uint32_t dst, const void* src) {
    asm volatile("cp.async.cg.shared.global [%0], [%1], 16;"
                 :: "r"(dst), "l"(src) : "memory");
}
#define CP_COMMIT() asm volatile("cp.async.commit_group;" ::: "memory")

#define LDMX4(r, addr)                                                      \
    asm volatile("ldmatrix.sync.aligned.m8n8.x4.shared.b16 "                \
        "{%0,%1,%2,%3}, [%4];"                                              \
        : "=r"((r)[0]), "=r"((r)[1]), "=r"((r)[2]), "=r"((r)[3])            \
        : "r"(addr))

#define MMA_FP16(d, a, b0, b1)                                              \
    asm volatile("mma.sync.aligned.m16n8k16.row.col.f32.f16.f16.f32 "      \
        "{%0,%1,%2,%3}, {%4,%5,%6,%7}, {%8,%9}, {%0,%1,%2,%3};"             \
        : "+f"((d)[0]), "+f"((d)[1]), "+f"((d)[2]), "+f"((d)[3])            \
        : "r"((a)[0]), "r"((a)[1]), "r"((a)[2]), "r"((a)[3]),               \
          "r"(b0), "r"(b1))

// ---------------- prep kernels ----------------
__global__ void deg_kernel(const int* __restrict__ ei, int E) {
    if (blockIdx.x == 0 && threadIdx.x == 0) g_total = 0;
    int e = blockIdx.x * blockDim.x + threadIdx.x;
    if (e < E) atomicAdd(&g_degi[ei[E + e]], 1);
}

// dis + CSR range allocation (unordered rowstart via atomic; valid partition)
__global__ void alloc_kernel(int n) {
    int i = blockIdx.x * blockDim.x + threadIdx.x;
    if (i < n) {
        int d = g_degi[i];
        g_dis[i] = rsqrtf(1.0f + (float)d);
        int r = atomicAdd(&g_total, d);
        g_rowstart[i] = r;
        g_rowend[i]   = r + d;
        g_cursor[i]   = r;
    }
}

__global__ void fill_kernel(const int* __restrict__ ei, int E) {
    int e = blockIdx.x * blockDim.x + threadIdx.x;
    if (e < E) {
        int dst = ei[E + e];
        int p = atomicAdd(&g_cursor[dst], 1);
        g_csr[p] = ei[e];
    }
}

__global__ void count_kernel(const int* __restrict__ bi, int n) {
    int i = blockIdx.x * blockDim.x + threadIdx.x;
    if (i < n) atomicAdd(&g_cnt[bi[i]], 1);
}

__global__ void gscan_kernel() {
    if (threadIdx.x == 0) {
        int s = 0;
        for (int g = 0; g < GG; g++) { g_start[g] = s; s += g_cnt[g]; }
    }
}

// ---------------- xs0 = fp16(dis * x), x is [N,128] fp32 ----------------
__global__ void conv_x0_kernel(const float* __restrict__ x, int n) {
    int i = blockIdx.x * blockDim.x + threadIdx.x;  // over n*64 half2
    if (i >= n * 64) return;
    int node = i >> 6;
    float d = g_dis[node];
    float2 a = reinterpret_cast<const float2*>(x)[i];
    reinterpret_cast<__half2*>(g_xs16)[i] = __floats2half2_rn(d * a.x, d * a.y);
}

// W [KD][256] -> transposed fp16 hi/lo splits at Wt[layer] [256][KD]
__global__ void conv_w_kernel(const float* __restrict__ W, int KD, int layer) {
    int i = blockIdx.x * blockDim.x + threadIdx.x;
    if (i >= KD * 256) return;
    int k = i >> 8;
    int n = i & 255;
    float w = W[i];
    __half h = __float2half_rn(w);
    size_t off = (size_t)layer * DD * DD + (size_t)n * KD + k;
    g_Wth[off] = h;
    g_Wtl[off] = __float2half_rn(w - __half2float(h));
}

// ---------------- CSR aggregate (fp16 gather, fp32 accum) --------------------
// Y[dst] = dis[dst] * (xs[dst] + sum_{src} xs[src]); write fp16 Y.
// 64 threads per node, 4 nodes per 256-thread block.
template<int KD>
__global__ void __launch_bounds__(256) aggregate_kernel(int n) {
    int node = blockIdx.x * 4 + (threadIdx.x >> 6);
    int f    = threadIdx.x & 63;
    if (node >= n) return;

    int s = g_rowstart[node];
    int e = g_rowend[node];
    const char* xs = (const char*)g_xs16;
    constexpr size_t ROWB = KD * 2;

    if constexpr (KD == 256) {
        uint2 sv = __ldg((const uint2*)(xs + (size_t)node * ROWB) + f);
        float2 a0 = __half22float2(*(__half2*)&sv.x);
        float2 a1 = __half22float2(*(__half2*)&sv.y);
        int i = s;
        for (; i + 4 <= e; i += 4) {
            int s0 = __ldg(&g_csr[i]);
            int s1 = __ldg(&g_csr[i + 1]);
            int s2 = __ldg(&g_csr[i + 2]);
            int s3 = __ldg(&g_csr[i + 3]);
            uint2 v0 = __ldg((const uint2*)(xs + (size_t)s0 * ROWB) + f);
            uint2 v1 = __ldg((const uint2*)(xs + (size_t)s1 * ROWB) + f);
            uint2 v2 = __ldg((const uint2*)(xs + (size_t)s2 * ROWB) + f);
            uint2 v3 = __ldg((const uint2*)(xs + (size_t)s3 * ROWB) + f);
            float2 t;
            t = __half22float2(*(__half2*)&v0.x); a0.x += t.x; a0.y += t.y;
            t = __half22float2(*(__half2*)&v0.y); a1.x += t.x; a1.y += t.y;
            t = __half22float2(*(__half2*)&v1.x); a0.x += t.x; a0.y += t.y;
            t = __half22float2(*(__half2*)&v1.y); a1.x += t.x; a1.y += t.y;
            t = __half22float2(*(__half2*)&v2.x); a0.x += t.x; a0.y += t.y;
            t = __half22float2(*(__half2*)&v2.y); a1.x += t.x; a1.y += t.y;
            t = __half22float2(*(__half2*)&v3.x); a0.x += t.x; a0.y += t.y;
            t = __half22float2(*(__half2*)&v3.y); a1.x += t.x; a1.y += t.y;
        }
        for (; i < e; i++) {
            int s0 = __ldg(&g_csr[i]);
            uint2 v = __ldg((const uint2*)(xs + (size_t)s0 * ROWB) + f);
            float2 t;
            t = __half22float2(*(__half2*)&v.x); a0.x += t.x; a0.y += t.y;
            t = __half22float2(*(__half2*)&v.y); a1.x += t.x; a1.y += t.y;
        }
        float d = g_dis[node];
        __half2 y0 = __floats2half2_rn(d * a0.x, d * a0.y);
        __half2 y1 = __floats2half2_rn(d * a1.x, d * a1.y);
        reinterpret_cast<uint2*>(g_Y16)[(size_t)node * 64 + f] =
            make_uint2(*reinterpret_cast<uint32_t*>(&y0),
                       *reinterpret_cast<uint32_t*>(&y1));
    } else {  // KD == 128
        uint32_t sv = __ldg((const uint32_t*)(xs + (size_t)node * ROWB) + f);
        float2 a0 = __half22float2(*(__half2*)&sv);
        int i = s;
        for (; i + 4 <= e; i += 4) {
            int s0 = __ldg(&g_csr[i]);
            int s1 = __ldg(&g_csr[i + 1]);
            int s2 = __ldg(&g_csr[i + 2]);
            int s3 = __ldg(&g_csr[i + 3]);
            uint32_t v0 = __ldg((const uint32_t*)(xs + (size_t)s0 * ROWB) + f);
            uint32_t v1 = __ldg((const uint32_t*)(xs + (size_t)s1 * ROWB) + f);
            uint32_t v2 = __ldg((const uint32_t*)(xs + (size_t)s2 * ROWB) + f);
            uint32_t v3 = __ldg((const uint32_t*)(xs + (size_t)s3 * ROWB) + f);
            float2 t;
            t = __half22float2(*(__half2*)&v0); a0.x += t.x; a0.y += t.y;
            t = __half22float2(*(__half2*)&v1); a0.x += t.x; a0.y += t.y;
            t = __half22float2(*(__half2*)&v2); a0.x += t.x; a0.y += t.y;
            t = __half22float2(*(__half2*)&v3); a0.x += t.x; a0.y += t.y;
        }
        for (; i < e; i++) {
            int s0 = __ldg(&g_csr[i]);
            uint32_t v = __ldg((const uint32_t*)(xs + (size_t)s0 * ROWB) + f);
            float2 t = __half22float2(*(__half2*)&v);
            a0.x += t.x; a0.y += t.y;
        }
        float d = g_dis[node];
        __half2 y = __floats2half2_rn(d * a0.x, d * a0.y);
        reinterpret_cast<uint32_t*>(g_Y16)[(size_t)node * 64 + f] =
            *reinterpret_cast<uint32_t*>(&y);
    }
}

// ---------------- fp16 2-product GEMM (mma.sync + ldmatrix + 3-stage cp.async)
// z = Y @ (Wh + Wl); act = tanh(z + b); xs16 = fp16(dis*act); LAST: act fp32.
#define ARRB 4096               // 128 rows * 32B
#define STGB (3 * ARRB)         // 12288 (A, Bh, Bl)
#define SM_TOTAL (3 * STGB)     // 36864

template<int KD, bool LAST>
__global__ void __launch_bounds__(256) gemm_mma(const __half* __restrict__ Wh,
                                                const __half* __restrict__ Wl,
                                                const float* __restrict__ bias, int M) {
    extern __shared__ char smc[];
    const uint32_t sb = smem_u32(smc);
    const int t    = threadIdx.x;
    const int lane = t & 31;
    const int w    = t >> 5;
    const int wm   = w & 3;
    const int wn   = w >> 2;
    const int m0   = blockIdx.y * 128;
    const int n0   = blockIdx.x * 128;

    float acc[2][8][4];
#pragma unroll
    for (int mt = 0; mt < 2; mt++)
#pragma unroll
        for (int nt = 0; nt < 8; nt++)
#pragma unroll
            for (int q = 0; q < 4; q++) acc[mt][nt][q] = 0.0f;

    // stage one 16-k chunk: 3 arrays x 128 rows x 2 chunks = 768 x 16B; 3/thread
    auto stage = [&](int c, int buf) {
#pragma unroll
        for (int j = 0; j < 3; j++) {
            int idx = t + j * 256;
            int arr = idx >> 8;       // 0=Y 1=Wh 2=Wl
            int rem = idx & 255;
            int row = rem >> 1;
            int cc  = rem & 1;
            const __half* src;
            int gr;
            if (arr == 0)      { src = g_Y16; gr = m0 + row; }
            else if (arr == 1) { src = Wh;    gr = n0 + row; }
            else               { src = Wl;    gr = n0 + row; }
            src += (size_t)gr * KD + c * 16 + cc * 8;
            uint32_t dst = sb + buf * STGB + arr * ARRB + row * 32 +
                           ((cc ^ ((row >> 2) & 1)) << 4);
            cp16(dst, src);
        }
        CP_COMMIT();
    };

    stage(0, 0);
    stage(1, 1);

    const int NCH = KD / 16;
    const int lr  = lane & 7;
    const int grp = lane >> 3;

    for (int c = 0; c < NCH; c++) {
        asm volatile("cp.async.wait_group 1;" ::: "memory");
        __syncthreads();
        int buf = c % 3;
        uint32_t sA  = sb + buf * STGB;
        uint32_t sBh = sA + ARRB;
        uint32_t sBl = sA + 2 * ARRB;

        uint32_t af[2][4];
#pragma unroll
        for (int mt = 0; mt < 2; mt++) {
            int row = wm * 32 + mt * 16 + lr + ((grp & 1) << 3);
            int cc  = grp >> 1;
            uint32_t off = row * 32 + ((cc ^ ((row >> 2) & 1)) << 4);
            LDMX4(af[mt], sA + off);
        }

        if (c + 2 < NCH) stage(c + 2, (c + 2) % 3);

#pragma unroll
        for (int ntp = 0; ntp < 4; ntp++) {
            int row = wn * 64 + ntp * 16 + lr + ((grp >> 1) << 3);
            int cc  = grp & 1;
            uint32_t off = row * 32 + ((cc ^ ((row >> 2) & 1)) << 4);
            uint32_t bh[4], bl[4];
            LDMX4(bh, sBh + off);
            LDMX4(bl, sBl + off);
#pragma unroll
            for (int mt = 0; mt < 2; mt++) {
                MMA_FP16(acc[mt][2 * ntp],     af[mt], bh[0], bh[1]);
                MMA_FP16(acc[mt][2 * ntp],     af[mt], bl[0], bl[1]);
                MMA_FP16(acc[mt][2 * ntp + 1], af[mt], bh[2], bh[3]);
                MMA_FP16(acc[mt][2 * ntp + 1], af[mt], bl[2], bl[3]);
            }
        }
    }

    // epilogue
    float* actout = (float*)g_act4;
#pragma unroll
    for (int mt = 0; mt < 2; mt++) {
        int r0 = m0 + wm * 32 + mt * 16 + (lane >> 2);
        int r1 = r0 + 8;
        float d0 = (r0 < M) ? g_dis[r0] : 0.0f;
        float d1 = (r1 < M) ? g_dis[r1] : 0.0f;
#pragma unroll
        for (int nt = 0; nt < 8; nt++) {
            int nc = n0 + wn * 64 + nt * 8 + (lane & 3) * 2;
            float b0 = __ldg(&bias[nc]);
            float b1 = __ldg(&bias[nc + 1]);
            if (r0 < M) {
                float t0 = tanhf(acc[mt][nt][0] + b0);
                float t1 = tanhf(acc[mt][nt][1] + b1);
                if (LAST) {
                    *reinterpret_cast<float2*>(actout + (size_t)r0 * DD + nc) =
                        make_float2(t0, t1);
                } else {
                    *reinterpret_cast<__half2*>(g_xs16 + (size_t)r0 * DD + nc) =
                        __floats2half2_rn(d0 * t0, d0 * t1);
                }
            }
            if (r1 < M) {
                float t2 = tanhf(acc[mt][nt][2] + b0);
                float t3 = tanhf(acc[mt][nt][3] + b1);
                if (LAST) {
                    *reinterpret_cast<float2*>(actout + (size_t)r1 * DD + nc) =
                        make_float2(t2, t3);
                } else {
                    *reinterpret_cast<__half2*>(g_xs16 + (size_t)r1 * DD + nc) =
                        __floats2half2_rn(d1 * t2, d1 * t3);
                }
            }
        }
    }
}

// ---------------- per-graph max + mean pooling ----------------
__global__ void pool_kernel() {
    int g = blockIdx.x;
    int f = threadIdx.x;
    int s = g_start[g];
    int c = g_cnt[g];
    const float* act = (const float*)g_act4;
    float mx = -INFINITY, sm = 0.f;
    for (int r = 0; r < c; r++) {
        float v = act[(size_t)(s + r) * DD + f];
        mx = fmaxf(mx, v);
        sm += v;
    }
    g_pool[g * (2 * DD) + f]      = mx;
    g_pool[g * (2 * DD) + DD + f] = sm / fmaxf((float)c, 1.0f);
}

// ---------------- tiny MLP ----------------
template<bool RELU>
__global__ void mlp_kernel(const float* __restrict__ A, const float* __restrict__ W,
                           const float* __restrict__ bias, float* __restrict__ C,
                           int K, int Nc) {
    __shared__ float sA[512];
    int row = blockIdx.x;
    for (int k = threadIdx.x; k < K; k += blockDim.x) sA[k] = A[(size_t)row * K + k];
    __syncthreads();
    for (int n = threadIdx.x; n < Nc; n += blockDim.x) {
        float acc = bias[n];
        for (int k = 0; k < K; k++) acc = fmaf(sA[k], W[(size_t)k * Nc + n], acc);
        C[(size_t)row * Nc + n] = RELU ? fmaxf(acc, 0.f) : acc;
    }
}

// ---------------- launch ----------------
extern "C" void kernel_launch(void* const* d_in, const int* in_sizes, int n_in,
                              void* d_out, int out_size) {
    const float* x   = (const float*)d_in[0];
    const int*   ei  = (const int*)d_in[1];
    const int*   bi  = (const int*)d_in[2];
    const float* W0 = (const float*)d_in[3];  const float* b0 = (const float*)d_in[4];
    const float* W1 = (const float*)d_in[5];  const float* b1 = (const float*)d_in[6];
    const float* W2 = (const float*)d_in[7];  const float* b2 = (const float*)d_in[8];
    const float* W3 = (const float*)d_in[9];  const float* b3 = (const float*)d_in[10];
    const float* fc1w = (const float*)d_in[11]; const float* fc1b = (const float*)d_in[12];
    const float* fc2w = (const float*)d_in[13]; const float* fc2b = (const float*)d_in[14];
    const float* ow   = (const float*)d_in[15]; const float* ob   = (const float*)d_in[16];

    const int F = 128;
    int N = in_sizes[0] / F;
    int E = in_sizes[1] / 2;
    int NB = (N + 255) / 256;

    void *p_degi, *p_cnt, *p_pool, *p_m1, *p_m2, *p_wh, *p_wl;
    cudaGetSymbolAddress(&p_degi, g_degi);
    cudaGetSymbolAddress(&p_cnt,  g_cnt);
    cudaGetSymbolAddress(&p_pool, g_pool);
    cudaGetSymbolAddress(&p_m1,   g_m1);
    cudaGetSymbolAddress(&p_m2,   g_m2);
    cudaGetSymbolAddress(&p_wh,   g_Wth);
    cudaGetSymbolAddress(&p_wl,   g_Wtl);

    dim3 ggrid(2, (N + 127) / 128);
    int ablocks = (N + 3) / 4;

    // prep (short chain so ncu's skip-5 lands on aggregate/gemm)
    cudaMemsetAsync(p_degi, 0, (size_t)N * sizeof(int), 0);
    deg_kernel<<<(E + 255) / 256, 256>>>(ei, E);
    alloc_kernel<<<NB, 256>>>(N);
    conv_x0_kernel<<<(N * 64 + 255) / 256, 256>>>(x, N);
    fill_kernel<<<(E + 255) / 256, 256>>>(ei, E);

    aggregate_kernel<128><<<ablocks, 256>>>(N);

    // all W splits upfront
    conv_w_kernel<<<(128 * 256 + 255) / 256, 256>>>(W0, 128, 0);
    conv_w_kernel<<<(256 * 256 + 255) / 256, 256>>>(W1, 256, 1);
    conv_w_kernel<<<(256 * 256 + 255) / 256, 256>>>(W2, 256, 2);
    conv_w_kernel<<<(256 * 256 + 255) / 256, 256>>>(W3, 256, 3);

    const __half* wh = (const __half*)p_wh;
    const __half* wl = (const __half*)p_wl;

    gemm_mma<128, false><<<ggrid, 256, SM_TOTAL>>>(wh, wl, b0, N);

    aggregate_kernel<256><<<ablocks, 256>>>(N);
    gemm_mma<256, false><<<ggrid, 256, SM_TOTAL>>>(wh + DD * DD, wl + DD * DD, b1, N);

    aggregate_kernel<256><<<ablocks, 256>>>(N);
    gemm_mma<256, false><<<ggrid, 256, SM_TOTAL>>>(wh + 2 * DD * DD, wl + 2 * DD * DD, b2, N);

    aggregate_kernel<256><<<ablocks, 256>>>(N);
    gemm_mma<256, true><<<ggrid, 256, SM_TOTAL>>>(wh + 3 * DD * DD, wl + 3 * DD * DD, b3, N);

    // batch bookkeeping + pooling + MLP
    cudaMemsetAsync(p_cnt, 0, GG * sizeof(int), 0);
    count_kernel<<<NB, 256>>>(bi, N);
    gscan_kernel<<<1, 32>>>();
    pool_kernel<<<GG, DD>>>();
    mlp_kernel<true ><<<GG, 256>>>((const float*)p_pool, fc1w, fc1b, (float*)p_m1, 2 * DD, 512);
    mlp_kernel<true ><<<GG, 256>>>((const float*)p_m1,   fc2w, fc2b, (float*)p_m2, 512, 256);
    mlp_kernel<false><<<GG, 32 >>>((const float*)p_m2,   ow,   ob,   (float*)d_out, 256, 10);
}

// round 10
// speedup vs baseline: 3.0794x; 1.0153x over previous
#include <cuda_runtime.h>
#include <cuda_fp16.h>
#include <cstdint>
#include <math.h>

#define NN 50000
#define EE 1600000
#define DD 256
#define GG 64

// ---------------- static device scratch ----------------
__device__ float4 g_act4[NN * DD / 4];        // final activation (fp32, pooling)
__device__ __half g_xs16[(NN + 128) * DD];    // xs = dis*act (fp16 gather array)
__device__ __half g_Y16[(NN + 128) * DD];     // Y = GEMM input (fp16)
__device__ __half g_Wth[4 * DD * DD];         // per-layer W^T hi (fp16)  [n][k]
__device__ __half g_Wtl[4 * DD * DD];         // per-layer W^T lo residual (fp16)
__device__ float  g_dis[NN];
__device__ int    g_degi[NN];
__device__ int    g_total;
__device__ int    g_rowstart[NN];
__device__ int    g_rowend[NN];
__device__ int    g_cursor[NN];
__device__ int    g_csr[EE];
__device__ int    g_cnt[GG];
__device__ int    g_start[GG];
__device__ float  g_pool[GG * 2 * DD];
__device__ float  g_m1[GG * 512];
__device__ float  g_m2[GG * 256];

// ---------------- small helpers ----------------
__device__ __forceinline__ uint32_t smem_u32(const void* p) {
    uint32_t a;
    asm("{ .reg .u64 t; cvta.to.shared.u64 t, %1; cvt.u32.u64 %0, t; }"
        : "=r"(a) : "l"(p));
    return a;
}

__device__ __forceinline__ void cp16(uint32_t dst, const void* src) {
    asm volatile("cp.async.cg.shared.global [%0], [%1], 16;"
                 :: "r"(dst), "l"(src) : "memory");
}
#define CP_COMMIT() asm volatile("cp.async.commit_group;" ::: "memory")

#define LDMX4(r, addr)                                                      \
    asm volatile("ldmatrix.sync.aligned.m8n8.x4.shared.b16 "                \
        "{%0,%1,%2,%3}, [%4];"                                              \
        : "=r"((r)[0]), "=r"((r)[1]), "=r"((r)[2]), "=r"((r)[3])            \
        : "r"(addr))

#define MMA_FP16(d, a, b0, b1)                                              \
    asm volatile("mma.sync.aligned.m16n8k16.row.col.f32.f16.f16.f32 "      \
        "{%0,%1,%2,%3}, {%4,%5,%6,%7}, {%8,%9}, {%0,%1,%2,%3};"             \
        : "+f"((d)[0]), "+f"((d)[1]), "+f"((d)[2]), "+f"((d)[3])            \
        : "r"((a)[0]), "r"((a)[1]), "r"((a)[2]), "r"((a)[3]),               \
          "r"(b0), "r"(b1))

// ---------------- prep kernels ----------------
// degree histogram + batch-count fused into one sweep
__global__ void deg_kernel(const int* __restrict__ ei, const int* __restrict__ bi,
                           int E, int n) {
    int e = blockIdx.x * blockDim.x + threadIdx.x;
    if (e == 0) g_total = 0;
    if (e < E) atomicAdd(&g_degi[ei[E + e]], 1);
    if (e < n) atomicAdd(&g_cnt[bi[e]], 1);
}

// dis + CSR range allocation (unordered rowstart via atomic; valid partition)
__global__ void alloc_kernel(int n) {
    int i = blockIdx.x * blockDim.x + threadIdx.x;
    if (i < n) {
        int d = g_degi[i];
        g_dis[i] = rsqrtf(1.0f + (float)d);
        int r = atomicAdd(&g_total, d);
        g_rowstart[i] = r;
        g_rowend[i]   = r + d;
        g_cursor[i]   = r;
    }
}

__global__ void fill_kernel(const int* __restrict__ ei, int E) {
    int e = blockIdx.x * blockDim.x + threadIdx.x;
    if (e < E) {
        int dst = ei[E + e];
        int p = atomicAdd(&g_cursor[dst], 1);
        g_csr[p] = ei[e];
    }
}

__global__ void gscan_kernel() {
    if (threadIdx.x == 0) {
        int s = 0;
        for (int g = 0; g < GG; g++) { g_start[g] = s; s += g_cnt[g]; }
    }
}

// ---------------- xs0 = fp16(dis * x), x is [N,128] fp32 ----------------
__global__ void conv_x0_kernel(const float* __restrict__ x, int n) {
    int i = blockIdx.x * blockDim.x + threadIdx.x;  // over n*64 half2
    if (i >= n * 64) return;
    int node = i >> 6;
    float d = g_dis[node];
    float2 a = reinterpret_cast<const float2*>(x)[i];
    reinterpret_cast<__half2*>(g_xs16)[i] = __floats2half2_rn(d * a.x, d * a.y);
}

// W [KD][256] -> transposed fp16 hi/lo splits at Wt[layer] [256][KD]
__global__ void conv_w_kernel(const float* __restrict__ W, int KD, int layer) {
    int i = blockIdx.x * blockDim.x + threadIdx.x;
    if (i >= KD * 256) return;
    int k = i >> 8;
    int n = i & 255;
    float w = W[i];
    __half h = __float2half_rn(w);
    size_t off = (size_t)layer * DD * DD + (size_t)n * KD + k;
    g_Wth[off] = h;
    g_Wtl[off] = __float2half_rn(w - __half2float(h));
}

// ---------------- CSR aggregate (fp16 gather, fp32 accum) --------------------
// Y[dst] = dis[dst] * (xs[dst] + sum_{src} xs[src]); write fp16 Y.
// 64 threads per node, 4 nodes per 256-thread block.
template<int KD>
__global__ void __launch_bounds__(256) aggregate_kernel(int n) {
    int node = blockIdx.x * 4 + (threadIdx.x >> 6);
    int f    = threadIdx.x & 63;
    if (node >= n) return;

    int s = g_rowstart[node];
    int e = g_rowend[node];
    const char* xs = (const char*)g_xs16;
    constexpr size_t ROWB = KD * 2;

    if constexpr (KD == 256) {
        uint2 sv = __ldg((const uint2*)(xs + (size_t)node * ROWB) + f);
        float2 a0 = __half22float2(*(__half2*)&sv.x);
        float2 a1 = __half22float2(*(__half2*)&sv.y);
        int i = s;
        for (; i + 4 <= e; i += 4) {
            int s0 = __ldg(&g_csr[i]);
            int s1 = __ldg(&g_csr[i + 1]);
            int s2 = __ldg(&g_csr[i + 2]);
            int s3 = __ldg(&g_csr[i + 3]);
            uint2 v0 = __ldg((const uint2*)(xs + (size_t)s0 * ROWB) + f);
            uint2 v1 = __ldg((const uint2*)(xs + (size_t)s1 * ROWB) + f);
            uint2 v2 = __ldg((const uint2*)(xs + (size_t)s2 * ROWB) + f);
            uint2 v3 = __ldg((const uint2*)(xs + (size_t)s3 * ROWB) + f);
            float2 t;
            t = __half22float2(*(__half2*)&v0.x); a0.x += t.x; a0.y += t.y;
            t = __half22float2(*(__half2*)&v0.y); a1.x += t.x; a1.y += t.y;
            t = __half22float2(*(__half2*)&v1.x); a0.x += t.x; a0.y += t.y;
            t = __half22float2(*(__half2*)&v1.y); a1.x += t.x; a1.y += t.y;
            t = __half22float2(*(__half2*)&v2.x); a0.x += t.x; a0.y += t.y;
            t = __half22float2(*(__half2*)&v2.y); a1.x += t.x; a1.y += t.y;
            t = __half22float2(*(__half2*)&v3.x); a0.x += t.x; a0.y += t.y;
            t = __half22float2(*(__half2*)&v3.y); a1.x += t.x; a1.y += t.y;
        }
        for (; i < e; i++) {
            int s0 = __ldg(&g_csr[i]);
            uint2 v = __ldg((const uint2*)(xs + (size_t)s0 * ROWB) + f);
            float2 t;
            t = __half22float2(*(__half2*)&v.x); a0.x += t.x; a0.y += t.y;
            t = __half22float2(*(__half2*)&v.y); a1.x += t.x; a1.y += t.y;
        }
        float d = g_dis[node];
        __half2 y0 = __floats2half2_rn(d * a0.x, d * a0.y);
        __half2 y1 = __floats2half2_rn(d * a1.x, d * a1.y);
        reinterpret_cast<uint2*>(g_Y16)[(size_t)node * 64 + f] =
            make_uint2(*reinterpret_cast<uint32_t*>(&y0),
                       *reinterpret_cast<uint32_t*>(&y1));
    } else {  // KD == 128
        uint32_t sv = __ldg((const uint32_t*)(xs + (size_t)node * ROWB) + f);
        float2 a0 = __half22float2(*(__half2*)&sv);
        int i = s;
        for (; i + 4 <= e; i += 4) {
            int s0 = __ldg(&g_csr[i]);
            int s1 = __ldg(&g_csr[i + 1]);
            int s2 = __ldg(&g_csr[i + 2]);
            int s3 = __ldg(&g_csr[i + 3]);
            uint32_t v0 = __ldg((const uint32_t*)(xs + (size_t)s0 * ROWB) + f);
            uint32_t v1 = __ldg((const uint32_t*)(xs + (size_t)s1 * ROWB) + f);
            uint32_t v2 = __ldg((const uint32_t*)(xs + (size_t)s2 * ROWB) + f);
            uint32_t v3 = __ldg((const uint32_t*)(xs + (size_t)s3 * ROWB) + f);
            float2 t;
            t = __half22float2(*(__half2*)&v0); a0.x += t.x; a0.y += t.y;
            t = __half22float2(*(__half2*)&v1); a0.x += t.x; a0.y += t.y;
            t = __half22float2(*(__half2*)&v2); a0.x += t.x; a0.y += t.y;
            t = __half22float2(*(__half2*)&v3); a0.x += t.x; a0.y += t.y;
        }
        for (; i < e; i++) {
            int s0 = __ldg(&g_csr[i]);
            uint32_t v = __ldg((const uint32_t*)(xs + (size_t)s0 * ROWB) + f);
            float2 t = __half22float2(*(__half2*)&v);
            a0.x += t.x; a0.y += t.y;
        }
        float d = g_dis[node];
        __half2 y = __floats2half2_rn(d * a0.x, d * a0.y);
        reinterpret_cast<uint32_t*>(g_Y16)[(size_t)node * 64 + f] =
            *reinterpret_cast<uint32_t*>(&y);
    }
}

// ---------------- fp16 2-product GEMM (mma.sync + ldmatrix + 3-stage cp.async)
// z = Y @ (Wh + Wl); act = tanh(z + b); xs16 = fp16(dis*act); LAST: act fp32.
#define ARRB 4096               // 128 rows * 32B
#define STGB (3 * ARRB)         // 12288 (Y, Wh, Wl)
#define SM_TOTAL (3 * STGB)     // 36864

template<int KD, bool LAST>
__global__ void __launch_bounds__(256) gemm_mma(const __half* __restrict__ Wh,
                                                const __half* __restrict__ Wl,
                                                const float* __restrict__ bias, int M) {
    extern __shared__ char smc[];
    const uint32_t sb = smem_u32(smc);
    const int t    = threadIdx.x;
    const int lane = t & 31;
    const int w    = t >> 5;
    const int wm   = w & 3;
    const int wn   = w >> 2;
    const int m0   = blockIdx.y * 128;
    const int n0   = blockIdx.x * 128;

    float acc[2][8][4];
#pragma unroll
    for (int mt = 0; mt < 2; mt++)
#pragma unroll
        for (int nt = 0; nt < 8; nt++)
#pragma unroll
            for (int q = 0; q < 4; q++) acc[mt][nt][q] = 0.0f;

    // stage one 16-k chunk: 3 arrays x 128 rows x 2 chunks = 768 x 16B; 3/thread
    auto stage = [&](int c, int buf) {
#pragma unroll
        for (int j = 0; j < 3; j++) {
            int idx = t + j * 256;
            int arr = idx >> 8;       // 0=Y 1=Wh 2=Wl
            int rem = idx & 255;
            int row = rem >> 1;
            int cc  = rem & 1;
            const __half* src;
            int gr;
            if (arr == 0)      { src = g_Y16; gr = m0 + row; }
            else if (arr == 1) { src = Wh;    gr = n0 + row; }
            else               { src = Wl;    gr = n0 + row; }
            src += (size_t)gr * KD + c * 16 + cc * 8;
            uint32_t dst = sb + buf * STGB + arr * ARRB + row * 32 +
                           ((cc ^ ((row >> 2) & 1)) << 4);
            cp16(dst, src);
        }
        CP_COMMIT();
    };

    stage(0, 0);
    stage(1, 1);

    const int NCH = KD / 16;
    const int lr  = lane & 7;
    const int grp = lane >> 3;

    for (int c = 0; c < NCH; c++) {
        asm volatile("cp.async.wait_group 1;" ::: "memory");
        __syncthreads();
        int buf = c % 3;
        uint32_t sA  = sb + buf * STGB;
        uint32_t sBh = sA + ARRB;
        uint32_t sBl = sA + 2 * ARRB;

        uint32_t af[2][4];
#pragma unroll
        for (int mt = 0; mt < 2; mt++) {
            int row = wm * 32 + mt * 16 + lr + ((grp & 1) << 3);
            int cc  = grp >> 1;
            uint32_t off = row * 32 + ((cc ^ ((row >> 2) & 1)) << 4);
            LDMX4(af[mt], sA + off);
        }

        if (c + 2 < NCH) stage(c + 2, (c + 2) % 3);

#pragma unroll
        for (int ntp = 0; ntp < 4; ntp++) {
            int row = wn * 64 + ntp * 16 + lr + ((grp >> 1) << 3);
            int cc  = grp & 1;
            uint32_t off = row * 32 + ((cc ^ ((row >> 2) & 1)) << 4);
            uint32_t bh[4], bl[4];
            LDMX4(bh, sBh + off);
            LDMX4(bl, sBl + off);
#pragma unroll
            for (int mt = 0; mt < 2; mt++) {
                MMA_FP16(acc[mt][2 * ntp],     af[mt], bh[0], bh[1]);
                MMA_FP16(acc[mt][2 * ntp],     af[mt], bl[0], bl[1]);
                MMA_FP16(acc[mt][2 * ntp + 1], af[mt], bh[2], bh[3]);
                MMA_FP16(acc[mt][2 * ntp + 1], af[mt], bl[2], bl[3]);
            }
        }
    }

    // epilogue
    float* actout = (float*)g_act4;
#pragma unroll
    for (int mt = 0; mt < 2; mt++) {
        int r0 = m0 + wm * 32 + mt * 16 + (lane >> 2);
        int r1 = r0 + 8;
        float d0 = (r0 < M) ? g_dis[r0] : 0.0f;
        float d1 = (r1 < M) ? g_dis[r1] : 0.0f;
#pragma unroll
        for (int nt = 0; nt < 8; nt++) {
            int nc = n0 + wn * 64 + nt * 8 + (lane & 3) * 2;
            float b0 = __ldg(&bias[nc]);
            float b1 = __ldg(&bias[nc + 1]);
            if (r0 < M) {
                float t0 = tanhf(acc[mt][nt][0] + b0);
                float t1 = tanhf(acc[mt][nt][1] + b1);
                if (LAST) {
                    *reinterpret_cast<float2*>(actout + (size_t)r0 * DD + nc) =
                        make_float2(t0, t1);
                } else {
                    *reinterpret_cast<__half2*>(g_xs16 + (size_t)r0 * DD + nc) =
                        __floats2half2_rn(d0 * t0, d0 * t1);
                }
            }
            if (r1 < M) {
                float t2 = tanhf(acc[mt][nt][2] + b0);
                float t3 = tanhf(acc[mt][nt][3] + b1);
                if (LAST) {
                    *reinterpret_cast<float2*>(actout + (size_t)r1 * DD + nc) =
                        make_float2(t2, t3);
                } else {
                    *reinterpret_cast<__half2*>(g_xs16 + (size_t)r1 * DD + nc) =
                        __floats2half2_rn(d1 * t2, d1 * t3);
                }
            }
        }
    }
}

// ---------------- per-graph max + mean pooling (64-feature strips) ----------
__global__ void pool_kernel() {
    int g  = blockIdx.x;
    int fc = blockIdx.y;                 // feature chunk 0..3
    int f  = fc * 64 + threadIdx.x;
    int s  = g_start[g];
    int c  = g_cnt[g];
    const float* act = (const float*)g_act4;
    float mx = -INFINITY, sm = 0.f;
    for (int r = 0; r < c; r++) {
        float v = act[(size_t)(s + r) * DD + f];
        mx = fmaxf(mx, v);
        sm += v;
    }
    g_pool[g * (2 * DD) + f]      = mx;
    g_pool[g * (2 * DD) + DD + f] = sm / fmaxf((float)c, 1.0f);
}

// ---------------- tiny MLP ----------------
template<bool RELU>
__global__ void mlp_kernel(const float* __restrict__ A, const float* __restrict__ W,
                           const float* __restrict__ bias, float* __restrict__ C,
                           int K, int Nc) {
    __shared__ float sA[512];
    int row = blockIdx.x;
    for (int k = threadIdx.x; k < K; k += blockDim.x) sA[k] = A[(size_t)row * K + k];
    __syncthreads();
    for (int n = threadIdx.x; n < Nc; n += blockDim.x) {
        float acc = bias[n];
        for (int k = 0; k < K; k++) acc = fmaf(sA[k], W[(size_t)k * Nc + n], acc);
        C[(size_t)row * Nc + n] = RELU ? fmaxf(acc, 0.f) : acc;
    }
}

// ---------------- launch ----------------
extern "C" void kernel_launch(void* const* d_in, const int* in_sizes, int n_in,
                              void* d_out, int out_size) {
    const float* x   = (const float*)d_in[0];
    const int*   ei  = (const int*)d_in[1];
    const int*   bi  = (const int*)d_in[2];
    const float* W0 = (const float*)d_in[3];  const float* b0 = (const float*)d_in[4];
    const float* W1 = (const float*)d_in[5];  const float* b1 = (const float*)d_in[6];
    const float* W2 = (const float*)d_in[7];  const float* b2 = (const float*)d_in[8];
    const float* W3 = (const float*)d_in[9];  const float* b3 = (const float*)d_in[10];
    const float* fc1w = (const float*)d_in[11]; const float* fc1b = (const float*)d_in[12];
    const float* fc2w = (const float*)d_in[13]; const float* fc2b = (const float*)d_in[14];
    const float* ow   = (const float*)d_in[15]; const float* ob   = (const float*)d_in[16];

    const int F = 128;
    int N = in_sizes[0] / F;
    int E = in_sizes[1] / 2;
    int NB = (N + 255) / 256;

    void *p_degi, *p_cnt, *p_pool, *p_m1, *p_m2, *p_wh, *p_wl;
    cudaGetSymbolAddress(&p_degi, g_degi);
    cudaGetSymbolAddress(&p_cnt,  g_cnt);
    cudaGetSymbolAddress(&p_pool, g_pool);
    cudaGetSymbolAddress(&p_m1,   g_m1);
    cudaGetSymbolAddress(&p_m2,   g_m2);
    cudaGetSymbolAddress(&p_wh,   g_Wth);
    cudaGetSymbolAddress(&p_wl,   g_Wtl);

    dim3 ggrid(2, (N + 127) / 128);
    int ablocks = (N + 3) / 4;

    // prep
    cudaMemsetAsync(p_degi, 0, (size_t)N * sizeof(int), 0);
    cudaMemsetAsync(p_cnt, 0, GG * sizeof(int), 0);
    deg_kernel<<<(E + 255) / 256, 256>>>(ei, bi, E, N);
    alloc_kernel<<<NB, 256>>>(N);
    conv_x0_kernel<<<(N * 64 + 255) / 256, 256>>>(x, N);
    fill_kernel<<<(E + 255) / 256, 256>>>(ei, E);
    gscan_kernel<<<1, 32>>>();

    aggregate_kernel<128><<<ablocks, 256>>>(N);

    // all W splits upfront
    conv_w_kernel<<<(128 * 256 + 255) / 256, 256>>>(W0, 128, 0);
    conv_w_kernel<<<(256 * 256 + 255) / 256, 256>>>(W1, 256, 1);
    conv_w_kernel<<<(256 * 256 + 255) / 256, 256>>>(W2, 256, 2);
    conv_w_kernel<<<(256 * 256 + 255) / 256, 256>>>(W3, 256, 3);

    const __half* wh = (const __half*)p_wh;
    const __half* wl = (const __half*)p_wl;

    gemm_mma<128, false><<<ggrid, 256, SM_TOTAL>>>(wh, wl, b0, N);

    aggregate_kernel<256><<<ablocks, 256>>>(N);
    gemm_mma<256, false><<<ggrid, 256, SM_TOTAL>>>(wh + DD * DD, wl + DD * DD, b1, N);

    aggregate_kernel<256><<<ablocks, 256>>>(N);
    gemm_mma<256, false><<<ggrid, 256, SM_TOTAL>>>(wh + 2 * DD * DD, wl + 2 * DD * DD, b2, N);

    aggregate_kernel<256><<<ablocks, 256>>>(N);
    gemm_mma<256, true><<<ggrid, 256, SM_TOTAL>>>(wh + 3 * DD * DD, wl + 3 * DD * DD, b3, N);

    // pooling + MLP
    pool_kernel<<<dim3(GG, 4), 64>>>();
    mlp_kernel<true ><<<GG, 256>>>((const float*)p_pool, fc1w, fc1b, (float*)p_m1, 2 * DD, 512);
    mlp_kernel<true ><<<GG, 256>>>((const float*)p_m1,   fc2w, fc2b, (float*)p_m2, 512, 256);
    mlp_kernel<false><<<GG, 32 >>>((const float*)p_m2,   ow,   ob,   (float*)d_out, 256, 10);
}